// round 11
// baseline (speedup 1.0000x reference)
#include <cuda_runtime.h>
#include <cuda_fp16.h>

#define B_SZ   16
#define NUM_CN 25000
#define NUM_VN 50000
#define NUM_E  200000
#define D_EMB  16
#define D_HID  32
#define D_MSG  16

typedef unsigned long long ULL;

// ---- scratch (device globals) ----
__device__ __half g_hf_x[(size_t)NUM_CN * B_SZ * D_HID];   // [CN][B][32] fp16
__device__ __half g_hf_z[(size_t)NUM_CN * B_SZ * D_HID];
__device__ __half g_s[(size_t)2 * B_SZ * NUM_VN * D_HID];  // [pol][b][VN][32] fp16
__device__ float  g_M[2 * 32 * 32];                        // Mx | Mz combined mats
__device__ int      g_cnt[4 * NUM_VN];                     // deg_x|deg_z|cur_x|cur_z
__device__ int      g_offs_x[NUM_VN + 1], g_offs_z[NUM_VN + 1];
__device__ unsigned g_csr_x[NUM_E],   g_csr_z[NUM_E];      // f | (mask<<16)
__device__ unsigned g_mask_x[NUM_CN], g_mask_z[NUM_CN];

// ---------------------------------------------------------------------------
// f32x2 packed helpers
__device__ __forceinline__ ULL pk2(float x) {
    ULL d; asm("mov.b64 %0, {%1, %1};" : "=l"(d) : "f"(x)); return d;
}
__device__ __forceinline__ ULL pkp(float x, float y) {
    ULL d; asm("mov.b64 %0, {%1, %2};" : "=l"(d) : "f"(x), "f"(y)); return d;
}
__device__ __forceinline__ float2 up2(ULL a) {
    float lo, hi; asm("mov.b64 {%0, %1}, %2;" : "=f"(lo), "=f"(hi) : "l"(a));
    return make_float2(lo, hi);
}
__device__ __forceinline__ ULL f2fma(ULL a, ULL b, ULL c) {
    ULL d; asm("fma.rn.f32x2 %0, %1, %2, %3;" : "=l"(d) : "l"(a), "l"(b), "l"(c));
    return d;
}
__device__ __forceinline__ float4 mk4(ULL a, ULL b) {
    float2 p = up2(a), q = up2(b);
    return make_float4(p.x, p.y, q.x, q.y);
}

// ---------------------------------------------------------------------------
// kernel 1: degree histogram + syndrome bitmask pack
__global__ void __launch_bounds__(256) prep_kernel(
    const int* __restrict__ to_x, const int* __restrict__ to_z,
    const int* __restrict__ syn_x, const int* __restrict__ syn_z,
    int* __restrict__ deg_x, int* __restrict__ deg_z,
    unsigned* __restrict__ mask_x, unsigned* __restrict__ mask_z)
{
    int i = blockIdx.x * 256 + threadIdx.x;
    if (i < NUM_E) {
        atomicAdd(&deg_x[__ldg(to_x + i)], 1);
        atomicAdd(&deg_z[__ldg(to_z + i)], 1);
    }
    if (i < NUM_CN) {
        unsigned mx = 0, mz = 0;
        #pragma unroll
        for (int b = 0; b < B_SZ; b++) {
            mx |= (unsigned)(__ldg(syn_x + (size_t)b * NUM_CN + i) & 1) << b;
            mz |= (unsigned)(__ldg(syn_z + (size_t)b * NUM_CN + i) & 1) << b;
        }
        mask_x[i] = mx;
        mask_z[i] = mz;
    }
}

// ---------------------------------------------------------------------------
// kernel 2: exclusive scan (blocks 0,1) + combined-matrix precompute (block 2)
__global__ void __launch_bounds__(1024) scan_kernel(
    const int* __restrict__ deg_x, const int* __restrict__ deg_z,
    int* __restrict__ offs_x, int* __restrict__ offs_z,
    const float* __restrict__ Wx2, const float* __restrict__ Wz2,
    const float* __restrict__ We1, float* __restrict__ M)
{
    if (blockIdx.x == 2) {
        int t = threadIdx.x;
        #pragma unroll
        for (int r = 0; r < 2; r++) {
            int el = r * 1024 + t;            // 0..2047
            int pol = el >> 10;               // 0: Mx, 1: Mz
            int i = (el >> 5) & 31;           // row (s dim)
            int j = el & 31;                  // col (hid dim)
            const float* W2 = pol ? Wz2 : Wx2;
            const float* E1 = We1 + pol * 16 * 32;
            float sum = 0.f;
            #pragma unroll
            for (int k = 0; k < 16; k++)
                sum += W2[i * 16 + k] * E1[k * 32 + j];
            M[el] = sum;
        }
        return;
    }

    const int* deg  = blockIdx.x == 0 ? deg_x  : deg_z;
    int*       offs = blockIdx.x == 0 ? offs_x : offs_z;

    __shared__ int wt[32];
    __shared__ int sbase;
    int t = threadIdx.x;
    int lane = t & 31, w = t >> 5;
    if (t == 0) sbase = 0;
    __syncthreads();

    for (int c = 0; c < NUM_VN; c += 1024) {
        int gid = c + t;
        int x = (gid < NUM_VN) ? deg[gid] : 0;
        #pragma unroll
        for (int o = 1; o < 32; o <<= 1) {
            int y = __shfl_up_sync(0xffffffffu, x, o);
            if (lane >= o) x += y;
        }
        if (lane == 31) wt[w] = x;
        __syncthreads();
        if (w == 0) {
            int y = wt[lane];
            #pragma unroll
            for (int o = 1; o < 32; o <<= 1) {
                int z = __shfl_up_sync(0xffffffffu, y, o);
                if (lane >= o) y += z;
            }
            wt[lane] = y;
        }
        __syncthreads();
        int incl = x + (w > 0 ? wt[w - 1] : 0) + sbase;
        if (gid < NUM_VN) offs[gid + 1] = incl;
        __syncthreads();
        if (t == 1023) sbase = incl;
        __syncthreads();
    }
    if (t == 0) offs[0] = 0;
}

// ---------------------------------------------------------------------------
// kernel 3: fused CSR fill (y=2) + node partials (y=0,1)
__global__ void __launch_bounds__(256) fill_np_kernel(
    const int* __restrict__ from_x, const int* __restrict__ to_x,
    const int* __restrict__ from_z, const int* __restrict__ to_z,
    const int* __restrict__ offs_x, const int* __restrict__ offs_z,
    const unsigned* __restrict__ mask_x, const unsigned* __restrict__ mask_z,
    int* __restrict__ cur_x, int* __restrict__ cur_z,
    unsigned* __restrict__ csr_x, unsigned* __restrict__ csr_z,
    const float* __restrict__ hx, const float* __restrict__ hz,
    const float* __restrict__ Wx1, const float* __restrict__ Wz1,
    __half* __restrict__ ox, __half* __restrict__ oz)
{
    if (blockIdx.y == 2) {
        int e = blockIdx.x * 256 + threadIdx.x;
        if (e >= NUM_E) return;
        {
            int v = __ldg(to_x + e);
            int f = __ldg(from_x + e);
            int p = atomicAdd(&cur_x[v], 1);
            csr_x[__ldg(offs_x + v) + p] = (unsigned)f | (__ldg(mask_x + f) << 16);
        }
        {
            int v = __ldg(to_z + e);
            int f = __ldg(from_z + e);
            int p = atomicAdd(&cur_z[v], 1);
            csr_z[__ldg(offs_z + v) + p] = (unsigned)f | (__ldg(mask_z + f) << 16);
        }
        return;
    }

    const float* h  = blockIdx.y == 0 ? hx  : hz;
    const float* W1 = blockIdx.y == 0 ? Wx1 : Wz1;
    __half*      o  = blockIdx.y == 0 ? ox  : oz;

    __shared__ float4 sW1[128];   // W1 rows 0..15 (16x32)
    int t = threadIdx.x;
    if (t < 128) sW1[t] = reinterpret_cast<const float4*>(W1)[t];
    __syncthreads();

    int wid = t >> 5;
    int unit = blockIdx.x * 8 + wid;          // n*4 + bgroup, < 100000
    if (unit >= NUM_CN * 4) return;
    int n = unit >> 2;
    int b = ((unit & 3) << 2) | ((t >> 3) & 3);
    int chunk = t & 7;

    const float4* ph = reinterpret_cast<const float4*>(h + ((size_t)b * NUM_CN + n) * D_EMB);
    float4 h0 = ph[0], h1 = ph[1], h2 = ph[2], h3 = ph[3];
    float hr[16] = {h0.x,h0.y,h0.z,h0.w, h1.x,h1.y,h1.z,h1.w,
                    h2.x,h2.y,h2.z,h2.w, h3.x,h3.y,h3.z,h3.w};

    ULL a0 = 0ull, a1 = 0ull;
    #pragma unroll
    for (int d = 0; d < 16; d++) {
        float4 w = sW1[d*8 + chunk];
        ULL hd = pk2(hr[d]);
        a0 = f2fma(hd, pkp(w.x, w.y), a0);
        a1 = f2fma(hd, pkp(w.z, w.w), a1);
    }

    __half2 lo = __float22half2_rn(up2(a0));
    __half2 hi = __float22half2_rn(up2(a1));
    uint2 st;
    st.x = *reinterpret_cast<unsigned*>(&lo);
    st.y = *reinterpret_cast<unsigned*>(&hi);
    reinterpret_cast<uint2*>(o)[((size_t)n * B_SZ + b) * 8 + chunk] = st;
}

// ---------------------------------------------------------------------------
// kernel 4 (PROFILED SLOT): msg kernel — half-batch warps.
// warp-unit = (v, half); half picks b in [half*8, half*8+8).
// lane = b_local*4 + chunk4; lane owns hidden dims chunk4*8..+8 (one uint4).
// Per edge: ONE uniform csr load + ONE contiguous 512B warp gather.
__global__ void __launch_bounds__(256) msg_kernel(
    const float* __restrict__ h_to,
    const __half* __restrict__ hfx, const __half* __restrict__ hfz,
    const int* __restrict__ offs_x, const unsigned* __restrict__ csr_x,
    const int* __restrict__ offs_z, const unsigned* __restrict__ csr_z,
    const float* __restrict__ Wx1, const float* __restrict__ Wz1,
    __half* __restrict__ s_out)
{
    int pol = blockIdx.y;
    const uint4*    hf4  = reinterpret_cast<const uint4*>(pol ? hfz : hfx);
    const int*      offs = pol ? offs_z : offs_x;
    const unsigned* csr  = pol ? csr_z  : csr_x;

    __shared__ float4 sW1[128];   // W1 rows 16..31 (16x32)
    {
        const float4* w1 = reinterpret_cast<const float4*>((pol ? Wz1 : Wx1) + 16 * 32);
        int t = threadIdx.x;
        if (t < 128) sW1[t] = w1[t];
    }
    __syncthreads();

    int t = threadIdx.x;
    int wid = t >> 5;
    int lane = t & 31;
    int unit = blockIdx.x * 8 + wid;          // < 100000 (grid.x = 12500)
    int v = unit >> 1;
    int half = unit & 1;
    int b_local = lane >> 2;                  // 0..7
    int chunk4 = lane & 3;                    // 0..3
    int b = half * 8 + b_local;

    // hp = h_to[b][v] @ W1[16:32], lane's 8 hidden dims (chunk4*8..+8)
    ULL a0 = 0ull, a1 = 0ull, a2 = 0ull, a3 = 0ull;
    {
        const float4* ph = reinterpret_cast<const float4*>(
            h_to + ((size_t)b * NUM_VN + v) * D_EMB);
        float4 h0 = ph[0], h1 = ph[1], h2 = ph[2], h3 = ph[3];
        float hr[16] = {h0.x,h0.y,h0.z,h0.w, h1.x,h1.y,h1.z,h1.w,
                        h2.x,h2.y,h2.z,h2.w, h3.x,h3.y,h3.z,h3.w};
        #pragma unroll
        for (int d = 0; d < 16; d++) {
            float4 w0 = sW1[d*8 + chunk4*2];
            float4 w1v = sW1[d*8 + chunk4*2 + 1];
            ULL hd = pk2(hr[d]);
            a0 = f2fma(hd, pkp(w0.x,  w0.y),  a0);
            a1 = f2fma(hd, pkp(w0.z,  w0.w),  a1);
            a2 = f2fma(hd, pkp(w1v.x, w1v.y), a2);
            a3 = f2fma(hd, pkp(w1v.z, w1v.w), a3);
        }
    }
    float2 hp0 = up2(a0), hp1 = up2(a1), hp2 = up2(a2), hp3 = up2(a3);

    float s0 = 0.f, s1 = 0.f, s2 = 0.f, s3 = 0.f;
    float s4 = 0.f, s5 = 0.f, s6 = 0.f, s7 = 0.f;

    int beg = __ldg(offs + v), end = __ldg(offs + v + 1);
    unsigned shift = 16 + b;
    unsigned lane_off = (unsigned)(half * 32 + lane);   // uint4 offset within hf row

    for (int e = beg; e < end; e += 2) {
        unsigned pka = __ldg(csr + e);
        unsigned pkb = (e + 1 < end) ? __ldg(csr + e + 1) : 0u;
        bool ga = (pka >> shift) & 1u;
        bool gb = (pkb >> shift) & 1u;
        uint4 va, vb;
        if (ga) va = __ldg(hf4 + (size_t)(pka & 0xFFFFu) * 64u + lane_off);
        if (gb) vb = __ldg(hf4 + (size_t)(pkb & 0xFFFFu) * 64u + lane_off);
        if (ga) {
            float2 p0 = __half22float2(*reinterpret_cast<__half2*>(&va.x));
            float2 p1 = __half22float2(*reinterpret_cast<__half2*>(&va.y));
            float2 p2 = __half22float2(*reinterpret_cast<__half2*>(&va.z));
            float2 p3 = __half22float2(*reinterpret_cast<__half2*>(&va.w));
            s0 += fmaxf(p0.x + hp0.x, 0.f);  s1 += fmaxf(p0.y + hp0.y, 0.f);
            s2 += fmaxf(p1.x + hp1.x, 0.f);  s3 += fmaxf(p1.y + hp1.y, 0.f);
            s4 += fmaxf(p2.x + hp2.x, 0.f);  s5 += fmaxf(p2.y + hp2.y, 0.f);
            s6 += fmaxf(p3.x + hp3.x, 0.f);  s7 += fmaxf(p3.y + hp3.y, 0.f);
        }
        if (gb) {
            float2 p0 = __half22float2(*reinterpret_cast<__half2*>(&vb.x));
            float2 p1 = __half22float2(*reinterpret_cast<__half2*>(&vb.y));
            float2 p2 = __half22float2(*reinterpret_cast<__half2*>(&vb.z));
            float2 p3 = __half22float2(*reinterpret_cast<__half2*>(&vb.w));
            s0 += fmaxf(p0.x + hp0.x, 0.f);  s1 += fmaxf(p0.y + hp0.y, 0.f);
            s2 += fmaxf(p1.x + hp1.x, 0.f);  s3 += fmaxf(p1.y + hp1.y, 0.f);
            s4 += fmaxf(p2.x + hp2.x, 0.f);  s5 += fmaxf(p2.y + hp2.y, 0.f);
            s6 += fmaxf(p3.x + hp3.x, 0.f);  s7 += fmaxf(p3.y + hp3.y, 0.f);
        }
    }

    // store raw s (8 halves = one uint4), layout [pol][b][VN][32]
    __half2 q0 = __float22half2_rn(make_float2(s0, s1));
    __half2 q1 = __float22half2_rn(make_float2(s2, s3));
    __half2 q2 = __float22half2_rn(make_float2(s4, s5));
    __half2 q3 = __float22half2_rn(make_float2(s6, s7));
    uint4 st;
    st.x = *reinterpret_cast<unsigned*>(&q0);
    st.y = *reinterpret_cast<unsigned*>(&q1);
    st.z = *reinterpret_cast<unsigned*>(&q2);
    st.w = *reinterpret_cast<unsigned*>(&q3);
    reinterpret_cast<uint4*>(s_out)[
        (((size_t)pol * B_SZ + b) * NUM_VN + v) * 4 + chunk4] = st;
}

// ---------------------------------------------------------------------------
// kernel 5: vn kernel — out = relu(sx@Mx + sz@Mz + h_to@We1[32:48]) @ We2
__global__ void __launch_bounds__(256) vn_kernel(
    const __half* __restrict__ s, const float* __restrict__ h_to,
    const float* __restrict__ M, const float* __restrict__ We1,
    const float* __restrict__ We2, float* __restrict__ out)
{
    __shared__ float4 sW1[640];   // 80 rows x 32 cols: Mx(32) | Mz(32) | We1[32:48](16)
    __shared__ float4 sW2[128];   // We2 32x16
    int t = threadIdx.x;
    for (int i = t; i < 512; i += 256) sW1[i] = reinterpret_cast<const float4*>(M)[i];
    if (t < 128) sW1[512 + t] = reinterpret_cast<const float4*>(We1 + 32 * 32)[t];
    if (t < 128) sW2[t] = reinterpret_cast<const float4*>(We2)[t];
    __syncthreads();

    int idx = blockIdx.x * 256 + t;   // idx = b*NUM_VN + v  (800000 = 3125*256)
    const size_t BVN = (size_t)B_SZ * NUM_VN;

    unsigned ux[16], uz[16];
    {
        const uint4* px = reinterpret_cast<const uint4*>(s) + (size_t)idx * 4;
        const uint4* pz = reinterpret_cast<const uint4*>(s) + (BVN + idx) * 4;
        #pragma unroll
        for (int q = 0; q < 4; q++) {
            uint4 a = px[q];
            ux[4*q+0]=a.x; ux[4*q+1]=a.y; ux[4*q+2]=a.z; ux[4*q+3]=a.w;
        }
        #pragma unroll
        for (int q = 0; q < 4; q++) {
            uint4 a = pz[q];
            uz[4*q+0]=a.x; uz[4*q+1]=a.y; uz[4*q+2]=a.z; uz[4*q+3]=a.w;
        }
    }
    float ft[16];
    {
        const float4* ph = reinterpret_cast<const float4*>(h_to + (size_t)idx * D_EMB);
        #pragma unroll
        for (int q = 0; q < 4; q++) {
            float4 a = ph[q];
            ft[4*q+0]=a.x; ft[4*q+1]=a.y; ft[4*q+2]=a.z; ft[4*q+3]=a.w;
        }
    }

    ULL acc[16];
    #pragma unroll
    for (int q = 0; q < 16; q++) acc[q] = 0ull;

    #pragma unroll
    for (int dp = 0; dp < 16; dp++) {
        float2 p = __half22float2(*reinterpret_cast<__half2*>(&ux[dp]));
        ULL f0 = pk2(p.x), f1 = pk2(p.y);
        const float4* r0 = &sW1[(2*dp) * 8];
        #pragma unroll
        for (int k = 0; k < 8; k++) {
            float4 w = r0[k];
            acc[2*k+0] = f2fma(f0, pkp(w.x, w.y), acc[2*k+0]);
            acc[2*k+1] = f2fma(f0, pkp(w.z, w.w), acc[2*k+1]);
        }
        const float4* r1 = &sW1[(2*dp+1) * 8];
        #pragma unroll
        for (int k = 0; k < 8; k++) {
            float4 w = r1[k];
            acc[2*k+0] = f2fma(f1, pkp(w.x, w.y), acc[2*k+0]);
            acc[2*k+1] = f2fma(f1, pkp(w.z, w.w), acc[2*k+1]);
        }
    }
    #pragma unroll
    for (int dp = 0; dp < 16; dp++) {
        float2 p = __half22float2(*reinterpret_cast<__half2*>(&uz[dp]));
        ULL f0 = pk2(p.x), f1 = pk2(p.y);
        const float4* r0 = &sW1[(32 + 2*dp) * 8];
        #pragma unroll
        for (int k = 0; k < 8; k++) {
            float4 w = r0[k];
            acc[2*k+0] = f2fma(f0, pkp(w.x, w.y), acc[2*k+0]);
            acc[2*k+1] = f2fma(f0, pkp(w.z, w.w), acc[2*k+1]);
        }
        const float4* r1 = &sW1[(32 + 2*dp+1) * 8];
        #pragma unroll
        for (int k = 0; k < 8; k++) {
            float4 w = r1[k];
            acc[2*k+0] = f2fma(f1, pkp(w.x, w.y), acc[2*k+0]);
            acc[2*k+1] = f2fma(f1, pkp(w.z, w.w), acc[2*k+1]);
        }
    }
    #pragma unroll
    for (int d = 0; d < 16; d++) {
        ULL fd = pk2(ft[d]);
        const float4* r = &sW1[(64 + d) * 8];
        #pragma unroll
        for (int k = 0; k < 8; k++) {
            float4 w = r[k];
            acc[2*k+0] = f2fma(fd, pkp(w.x, w.y), acc[2*k+0]);
            acc[2*k+1] = f2fma(fd, pkp(w.z, w.w), acc[2*k+1]);
        }
    }

    float hid[32];
    #pragma unroll
    for (int q = 0; q < 16; q++) {
        float2 p = up2(acc[q]);
        hid[2*q+0] = fmaxf(p.x, 0.f);
        hid[2*q+1] = fmaxf(p.y, 0.f);
    }

    ULL o[8];
    #pragma unroll
    for (int q = 0; q < 8; q++) o[q] = 0ull;
    #pragma unroll
    for (int j = 0; j < 32; j++) {
        ULL hj = pk2(hid[j]);
        #pragma unroll
        for (int k = 0; k < 4; k++) {
            float4 w = sW2[j*4 + k];
            o[2*k+0] = f2fma(hj, pkp(w.x, w.y), o[2*k+0]);
            o[2*k+1] = f2fma(hj, pkp(w.z, w.w), o[2*k+1]);
        }
    }

    float4* op = reinterpret_cast<float4*>(out + (size_t)idx * D_EMB);
    #pragma unroll
    for (int q = 0; q < 4; q++) op[q] = mk4(o[2*q], o[2*q+1]);
}

// ---------------------------------------------------------------------------
extern "C" void kernel_launch(void* const* d_in, const int* in_sizes, int n_in,
                              void* d_out, int out_size) {
    const float* h_from_x   = (const float*)d_in[0];
    const float* h_from_z   = (const float*)d_in[1];
    const float* h_to       = (const float*)d_in[2];
    const int*   syndrome_x = (const int*)d_in[3];
    const int*   syndrome_z = (const int*)d_in[4];
    const int*   from_ind_x = (const int*)d_in[5];
    const int*   to_ind_x   = (const int*)d_in[6];
    const int*   from_ind_z = (const int*)d_in[7];
    const int*   to_ind_z   = (const int*)d_in[8];
    const float* Wx1        = (const float*)d_in[9];
    const float* Wx2        = (const float*)d_in[10];
    const float* Wz1        = (const float*)d_in[11];
    const float* Wz2        = (const float*)d_in[12];
    const float* We1        = (const float*)d_in[13];
    const float* We2        = (const float*)d_in[14];
    float* out = (float*)d_out;

    __half *hf_x, *hf_z, *s;
    float *M;
    int *cnt, *offs_x, *offs_z;
    unsigned *csr_x, *csr_z, *mask_x, *mask_z;
    cudaGetSymbolAddress((void**)&hf_x, g_hf_x);
    cudaGetSymbolAddress((void**)&hf_z, g_hf_z);
    cudaGetSymbolAddress((void**)&s,    g_s);
    cudaGetSymbolAddress((void**)&M,    g_M);
    cudaGetSymbolAddress((void**)&cnt,  g_cnt);
    cudaGetSymbolAddress((void**)&offs_x, g_offs_x);
    cudaGetSymbolAddress((void**)&offs_z, g_offs_z);
    cudaGetSymbolAddress((void**)&csr_x, g_csr_x);
    cudaGetSymbolAddress((void**)&csr_z, g_csr_z);
    cudaGetSymbolAddress((void**)&mask_x, g_mask_x);
    cudaGetSymbolAddress((void**)&mask_z, g_mask_z);

    int *deg_x = cnt, *deg_z = cnt + NUM_VN;
    int *cur_x = cnt + 2 * NUM_VN, *cur_z = cnt + 3 * NUM_VN;

    cudaMemsetAsync(cnt, 0, 4 * NUM_VN * sizeof(int), 0);

    // k1: histogram + masks
    prep_kernel<<<(NUM_E + 255) / 256, 256>>>(
        to_ind_x, to_ind_z, syndrome_x, syndrome_z,
        deg_x, deg_z, mask_x, mask_z);

    // k2: scan (blocks 0,1) + combined-matrix precompute (block 2)
    scan_kernel<<<3, 1024>>>(deg_x, deg_z, offs_x, offs_z, Wx2, Wz2, We1, M);

    // k3: fused CSR fill (y=2) + node partials (y=0,1)
    fill_np_kernel<<<dim3(12500, 3), 256>>>(
        from_ind_x, to_ind_x, from_ind_z, to_ind_z,
        offs_x, offs_z, mask_x, mask_z, cur_x, cur_z, csr_x, csr_z,
        h_from_x, h_from_z, Wx1, Wz1, hf_x, hf_z);

    // k4 (profiled slot): messages — half-batch warps, one 512B gather/edge
    msg_kernel<<<dim3(12500, 2), 256>>>(
        h_to, hf_x, hf_z,
        offs_x, csr_x, offs_z, csr_z,
        Wx1, Wz1, s);

    // k5: vertex MLP with folded W2
    vn_kernel<<<(NUM_VN * B_SZ) / 256, 256>>>(s, h_to, M, We1, We2, out);
}

// round 12
// speedup vs baseline: 1.0144x; 1.0144x over previous
#include <cuda_runtime.h>
#include <cuda_fp16.h>

#define B_SZ   16
#define NUM_CN 25000
#define NUM_VN 50000
#define NUM_E  200000
#define D_EMB  16
#define D_HID  32
#define D_MSG  16

typedef unsigned long long ULL;

// ---- scratch (device globals) ----
__device__ __half g_hf_x[(size_t)NUM_CN * B_SZ * D_HID];   // [CN][B][32] fp16
__device__ __half g_hf_z[(size_t)NUM_CN * B_SZ * D_HID];
__device__ __half g_s[(size_t)2 * B_SZ * NUM_VN * D_HID];  // [pol][b][VN][32] fp16
__device__ float  g_M[2 * 32 * 32];                        // Mx | Mz combined mats
__device__ int      g_cnt[4 * NUM_VN];                     // deg_x|deg_z|cur_x|cur_z
__device__ int      g_offs_x[NUM_VN + 1], g_offs_z[NUM_VN + 1];
__device__ unsigned g_csr_x[NUM_E],   g_csr_z[NUM_E];      // f | (mask<<16)
__device__ unsigned g_mask_x[NUM_CN], g_mask_z[NUM_CN];

// ---------------------------------------------------------------------------
// f32x2 packed helpers
__device__ __forceinline__ ULL pk2(float x) {
    ULL d; asm("mov.b64 %0, {%1, %1};" : "=l"(d) : "f"(x)); return d;
}
__device__ __forceinline__ ULL pkp(float x, float y) {
    ULL d; asm("mov.b64 %0, {%1, %2};" : "=l"(d) : "f"(x), "f"(y)); return d;
}
__device__ __forceinline__ float2 up2(ULL a) {
    float lo, hi; asm("mov.b64 {%0, %1}, %2;" : "=f"(lo), "=f"(hi) : "l"(a));
    return make_float2(lo, hi);
}
__device__ __forceinline__ ULL f2fma(ULL a, ULL b, ULL c) {
    ULL d; asm("fma.rn.f32x2 %0, %1, %2, %3;" : "=l"(d) : "l"(a), "l"(b), "l"(c));
    return d;
}
__device__ __forceinline__ float4 mk4(ULL a, ULL b) {
    float2 p = up2(a), q = up2(b);
    return make_float4(p.x, p.y, q.x, q.y);
}

// ---------------------------------------------------------------------------
// kernel 1: degree histogram + syndrome bitmask pack
__global__ void __launch_bounds__(256) prep_kernel(
    const int* __restrict__ to_x, const int* __restrict__ to_z,
    const int* __restrict__ syn_x, const int* __restrict__ syn_z,
    int* __restrict__ deg_x, int* __restrict__ deg_z,
    unsigned* __restrict__ mask_x, unsigned* __restrict__ mask_z)
{
    int i = blockIdx.x * 256 + threadIdx.x;
    if (i < NUM_E) {
        atomicAdd(&deg_x[__ldg(to_x + i)], 1);
        atomicAdd(&deg_z[__ldg(to_z + i)], 1);
    }
    if (i < NUM_CN) {
        unsigned mx = 0, mz = 0;
        #pragma unroll
        for (int b = 0; b < B_SZ; b++) {
            mx |= (unsigned)(__ldg(syn_x + (size_t)b * NUM_CN + i) & 1) << b;
            mz |= (unsigned)(__ldg(syn_z + (size_t)b * NUM_CN + i) & 1) << b;
        }
        mask_x[i] = mx;
        mask_z[i] = mz;
    }
}

// ---------------------------------------------------------------------------
// kernel 2: exclusive scan (blocks 0,1) + combined-matrix precompute (block 2)
__global__ void __launch_bounds__(1024) scan_kernel(
    const int* __restrict__ deg_x, const int* __restrict__ deg_z,
    int* __restrict__ offs_x, int* __restrict__ offs_z,
    const float* __restrict__ Wx2, const float* __restrict__ Wz2,
    const float* __restrict__ We1, float* __restrict__ M)
{
    if (blockIdx.x == 2) {
        int t = threadIdx.x;
        #pragma unroll
        for (int r = 0; r < 2; r++) {
            int el = r * 1024 + t;            // 0..2047
            int pol = el >> 10;               // 0: Mx, 1: Mz
            int i = (el >> 5) & 31;           // row (s dim)
            int j = el & 31;                  // col (hid dim)
            const float* W2 = pol ? Wz2 : Wx2;
            const float* E1 = We1 + pol * 16 * 32;
            float sum = 0.f;
            #pragma unroll
            for (int k = 0; k < 16; k++)
                sum += W2[i * 16 + k] * E1[k * 32 + j];
            M[el] = sum;
        }
        return;
    }

    const int* deg  = blockIdx.x == 0 ? deg_x  : deg_z;
    int*       offs = blockIdx.x == 0 ? offs_x : offs_z;

    __shared__ int wt[32];
    __shared__ int sbase;
    int t = threadIdx.x;
    int lane = t & 31, w = t >> 5;
    if (t == 0) sbase = 0;
    __syncthreads();

    for (int c = 0; c < NUM_VN; c += 1024) {
        int gid = c + t;
        int x = (gid < NUM_VN) ? deg[gid] : 0;
        #pragma unroll
        for (int o = 1; o < 32; o <<= 1) {
            int y = __shfl_up_sync(0xffffffffu, x, o);
            if (lane >= o) x += y;
        }
        if (lane == 31) wt[w] = x;
        __syncthreads();
        if (w == 0) {
            int y = wt[lane];
            #pragma unroll
            for (int o = 1; o < 32; o <<= 1) {
                int z = __shfl_up_sync(0xffffffffu, y, o);
                if (lane >= o) y += z;
            }
            wt[lane] = y;
        }
        __syncthreads();
        int incl = x + (w > 0 ? wt[w - 1] : 0) + sbase;
        if (gid < NUM_VN) offs[gid + 1] = incl;
        __syncthreads();
        if (t == 1023) sbase = incl;
        __syncthreads();
    }
    if (t == 0) offs[0] = 0;
}

// ---------------------------------------------------------------------------
// kernel 3: fused CSR fill (y=2) + node partials (y=0,1)
__global__ void __launch_bounds__(256) fill_np_kernel(
    const int* __restrict__ from_x, const int* __restrict__ to_x,
    const int* __restrict__ from_z, const int* __restrict__ to_z,
    const int* __restrict__ offs_x, const int* __restrict__ offs_z,
    const unsigned* __restrict__ mask_x, const unsigned* __restrict__ mask_z,
    int* __restrict__ cur_x, int* __restrict__ cur_z,
    unsigned* __restrict__ csr_x, unsigned* __restrict__ csr_z,
    const float* __restrict__ hx, const float* __restrict__ hz,
    const float* __restrict__ Wx1, const float* __restrict__ Wz1,
    __half* __restrict__ ox, __half* __restrict__ oz)
{
    if (blockIdx.y == 2) {
        int e = blockIdx.x * 256 + threadIdx.x;
        if (e >= NUM_E) return;
        {
            int v = __ldg(to_x + e);
            int f = __ldg(from_x + e);
            int p = atomicAdd(&cur_x[v], 1);
            csr_x[__ldg(offs_x + v) + p] = (unsigned)f | (__ldg(mask_x + f) << 16);
        }
        {
            int v = __ldg(to_z + e);
            int f = __ldg(from_z + e);
            int p = atomicAdd(&cur_z[v], 1);
            csr_z[__ldg(offs_z + v) + p] = (unsigned)f | (__ldg(mask_z + f) << 16);
        }
        return;
    }

    const float* h  = blockIdx.y == 0 ? hx  : hz;
    const float* W1 = blockIdx.y == 0 ? Wx1 : Wz1;
    __half*      o  = blockIdx.y == 0 ? ox  : oz;

    __shared__ float4 sW1[128];   // W1 rows 0..15 (16x32)
    int t = threadIdx.x;
    if (t < 128) sW1[t] = reinterpret_cast<const float4*>(W1)[t];
    __syncthreads();

    int wid = t >> 5;
    int unit = blockIdx.x * 8 + wid;          // n*4 + bgroup, < 100000
    if (unit >= NUM_CN * 4) return;
    int n = unit >> 2;
    int b = ((unit & 3) << 2) | ((t >> 3) & 3);
    int chunk = t & 7;

    const float4* ph = reinterpret_cast<const float4*>(h + ((size_t)b * NUM_CN + n) * D_EMB);
    float4 h0 = ph[0], h1 = ph[1], h2 = ph[2], h3 = ph[3];
    float hr[16] = {h0.x,h0.y,h0.z,h0.w, h1.x,h1.y,h1.z,h1.w,
                    h2.x,h2.y,h2.z,h2.w, h3.x,h3.y,h3.z,h3.w};

    ULL a0 = 0ull, a1 = 0ull;
    #pragma unroll
    for (int d = 0; d < 16; d++) {
        float4 w = sW1[d*8 + chunk];
        ULL hd = pk2(hr[d]);
        a0 = f2fma(hd, pkp(w.x, w.y), a0);
        a1 = f2fma(hd, pkp(w.z, w.w), a1);
    }

    __half2 lo = __float22half2_rn(up2(a0));
    __half2 hi = __float22half2_rn(up2(a1));
    uint2 st;
    st.x = *reinterpret_cast<unsigned*>(&lo);
    st.y = *reinterpret_cast<unsigned*>(&hi);
    reinterpret_cast<uint2*>(o)[((size_t)n * B_SZ + b) * 8 + chunk] = st;
}

// ---------------------------------------------------------------------------
// kernel 4 (PROFILED SLOT): msg kernel — half-batch warps + predicated
// uint2 gathers (mask-skip preserved) + half2 edge math.
// warp-unit = (v, half); lane = b_local*8 + chunk; lane owns dims chunk*4..+4.
// bg in {0,1}: b = half*8 + bg*4 + b_local. Per edge: 1 uniform csr load +
// 2 independent PREDICATED 256B gathers (skip when syndrome bit clear).
__global__ void __launch_bounds__(256) msg_kernel(
    const float* __restrict__ h_to,
    const __half* __restrict__ hfx, const __half* __restrict__ hfz,
    const int* __restrict__ offs_x, const unsigned* __restrict__ csr_x,
    const int* __restrict__ offs_z, const unsigned* __restrict__ csr_z,
    const float* __restrict__ Wx1, const float* __restrict__ Wz1,
    __half* __restrict__ s_out)
{
    int pol = blockIdx.y;
    const uint2*    hf2  = reinterpret_cast<const uint2*>(pol ? hfz : hfx);
    const int*      offs = pol ? offs_z : offs_x;
    const unsigned* csr  = pol ? csr_z  : csr_x;

    __shared__ float4 sW1[128];   // W1 rows 16..31 (16x32)
    {
        const float4* w1 = reinterpret_cast<const float4*>((pol ? Wz1 : Wx1) + 16 * 32);
        int t = threadIdx.x;
        if (t < 128) sW1[t] = w1[t];
    }
    __syncthreads();

    int t = threadIdx.x;
    int wid = t >> 5;
    int lane = t & 31;
    int unit = blockIdx.x * 8 + wid;          // < 100000 (grid.x = 12500)
    int v = unit >> 1;
    int half = unit & 1;
    int b_local = (lane >> 3) & 3;            // 0..3
    int chunk = lane & 7;                     // 0..7, owns dims chunk*4..+4

    // hp for both b-groups (b = half*8 + bg*4 + b_local), stored as half2
    __half2 hp0[2], hp1[2];
    #pragma unroll
    for (int bg = 0; bg < 2; bg++) {
        int b = half * 8 + bg * 4 + b_local;
        const float4* ph = reinterpret_cast<const float4*>(
            h_to + ((size_t)b * NUM_VN + v) * D_EMB);
        float4 h0 = ph[0], h1 = ph[1], h2 = ph[2], h3 = ph[3];
        float hr[16] = {h0.x,h0.y,h0.z,h0.w, h1.x,h1.y,h1.z,h1.w,
                        h2.x,h2.y,h2.z,h2.w, h3.x,h3.y,h3.z,h3.w};
        ULL a0 = 0ull, a1 = 0ull;
        #pragma unroll
        for (int d = 0; d < 16; d++) {
            float4 w = sW1[d*8 + chunk];
            ULL hd = pk2(hr[d]);
            a0 = f2fma(hd, pkp(w.x, w.y), a0);
            a1 = f2fma(hd, pkp(w.z, w.w), a1);
        }
        hp0[bg] = __float22half2_rn(up2(a0));
        hp1[bg] = __float22half2_rn(up2(a1));
    }

    const __half2 z2 = __float2half2_rn(0.f);
    float s0[2] = {0,0}, s1[2] = {0,0}, s2[2] = {0,0}, s3[2] = {0,0};

    int beg = __ldg(offs + v), end = __ldg(offs + v + 1);
    unsigned shift0 = 16 + half * 8 + b_local;
    unsigned lane_off = (unsigned)((half * 8 + b_local) * 8 + chunk); // uint2 off, bg=0

    for (int e = beg; e < end; e += 2) {
        unsigned pka = __ldg(csr + e);
        unsigned pkb = (e + 1 < end) ? __ldg(csr + e + 1) : 0u;

        unsigned basea = (pka & 0xFFFFu) * 128u + lane_off;
        unsigned baseb = (pkb & 0xFFFFu) * 128u + lane_off;

        uint2 va[2], vb[2];
        bool ga[2], gb[2];
        #pragma unroll
        for (int bg = 0; bg < 2; bg++) {
            ga[bg] = (pka >> (shift0 + bg * 4)) & 1u;
            gb[bg] = (pkb >> (shift0 + bg * 4)) & 1u;
            if (ga[bg]) va[bg] = __ldg(hf2 + basea + bg * 32u);
            if (gb[bg]) vb[bg] = __ldg(hf2 + baseb + bg * 32u);
        }
        #pragma unroll
        for (int bg = 0; bg < 2; bg++) {
            if (ga[bg]) {
                __half2 r0 = __hmax2(__hadd2(*reinterpret_cast<__half2*>(&va[bg].x), hp0[bg]), z2);
                __half2 r1 = __hmax2(__hadd2(*reinterpret_cast<__half2*>(&va[bg].y), hp1[bg]), z2);
                float2 q0 = __half22float2(r0), q1 = __half22float2(r1);
                s0[bg] += q0.x;  s1[bg] += q0.y;
                s2[bg] += q1.x;  s3[bg] += q1.y;
            }
            if (gb[bg]) {
                __half2 r0 = __hmax2(__hadd2(*reinterpret_cast<__half2*>(&vb[bg].x), hp0[bg]), z2);
                __half2 r1 = __hmax2(__hadd2(*reinterpret_cast<__half2*>(&vb[bg].y), hp1[bg]), z2);
                float2 q0 = __half22float2(r0), q1 = __half22float2(r1);
                s0[bg] += q0.x;  s1[bg] += q0.y;
                s2[bg] += q1.x;  s3[bg] += q1.y;
            }
        }
    }

    // store raw s per bg (4 halves = one uint2), layout [pol][b][VN][32]
    #pragma unroll
    for (int bg = 0; bg < 2; bg++) {
        int b = half * 8 + bg * 4 + b_local;
        __half2 q0 = __float22half2_rn(make_float2(s0[bg], s1[bg]));
        __half2 q1 = __float22half2_rn(make_float2(s2[bg], s3[bg]));
        uint2 st;
        st.x = *reinterpret_cast<unsigned*>(&q0);
        st.y = *reinterpret_cast<unsigned*>(&q1);
        reinterpret_cast<uint2*>(s_out)[
            (((size_t)pol * B_SZ + b) * NUM_VN + v) * 8 + chunk] = st;
    }
}

// ---------------------------------------------------------------------------
// kernel 5: vn kernel — out = relu(sx@Mx + sz@Mz + h_to@We1[32:48]) @ We2
__global__ void __launch_bounds__(256) vn_kernel(
    const __half* __restrict__ s, const float* __restrict__ h_to,
    const float* __restrict__ M, const float* __restrict__ We1,
    const float* __restrict__ We2, float* __restrict__ out)
{
    __shared__ float4 sW1[640];   // 80 rows x 32 cols: Mx(32) | Mz(32) | We1[32:48](16)
    __shared__ float4 sW2[128];   // We2 32x16
    int t = threadIdx.x;
    for (int i = t; i < 512; i += 256) sW1[i] = reinterpret_cast<const float4*>(M)[i];
    if (t < 128) sW1[512 + t] = reinterpret_cast<const float4*>(We1 + 32 * 32)[t];
    if (t < 128) sW2[t] = reinterpret_cast<const float4*>(We2)[t];
    __syncthreads();

    int idx = blockIdx.x * 256 + t;   // idx = b*NUM_VN + v  (800000 = 3125*256)
    const size_t BVN = (size_t)B_SZ * NUM_VN;

    unsigned ux[16], uz[16];
    {
        const uint4* px = reinterpret_cast<const uint4*>(s) + (size_t)idx * 4;
        const uint4* pz = reinterpret_cast<const uint4*>(s) + (BVN + idx) * 4;
        #pragma unroll
        for (int q = 0; q < 4; q++) {
            uint4 a = px[q];
            ux[4*q+0]=a.x; ux[4*q+1]=a.y; ux[4*q+2]=a.z; ux[4*q+3]=a.w;
        }
        #pragma unroll
        for (int q = 0; q < 4; q++) {
            uint4 a = pz[q];
            uz[4*q+0]=a.x; uz[4*q+1]=a.y; uz[4*q+2]=a.z; uz[4*q+3]=a.w;
        }
    }
    float ft[16];
    {
        const float4* ph = reinterpret_cast<const float4*>(h_to + (size_t)idx * D_EMB);
        #pragma unroll
        for (int q = 0; q < 4; q++) {
            float4 a = ph[q];
            ft[4*q+0]=a.x; ft[4*q+1]=a.y; ft[4*q+2]=a.z; ft[4*q+3]=a.w;
        }
    }

    ULL acc[16];
    #pragma unroll
    for (int q = 0; q < 16; q++) acc[q] = 0ull;

    #pragma unroll
    for (int dp = 0; dp < 16; dp++) {
        float2 p = __half22float2(*reinterpret_cast<__half2*>(&ux[dp]));
        ULL f0 = pk2(p.x), f1 = pk2(p.y);
        const float4* r0 = &sW1[(2*dp) * 8];
        #pragma unroll
        for (int k = 0; k < 8; k++) {
            float4 w = r0[k];
            acc[2*k+0] = f2fma(f0, pkp(w.x, w.y), acc[2*k+0]);
            acc[2*k+1] = f2fma(f0, pkp(w.z, w.w), acc[2*k+1]);
        }
        const float4* r1 = &sW1[(2*dp+1) * 8];
        #pragma unroll
        for (int k = 0; k < 8; k++) {
            float4 w = r1[k];
            acc[2*k+0] = f2fma(f1, pkp(w.x, w.y), acc[2*k+0]);
            acc[2*k+1] = f2fma(f1, pkp(w.z, w.w), acc[2*k+1]);
        }
    }
    #pragma unroll
    for (int dp = 0; dp < 16; dp++) {
        float2 p = __half22float2(*reinterpret_cast<__half2*>(&uz[dp]));
        ULL f0 = pk2(p.x), f1 = pk2(p.y);
        const float4* r0 = &sW1[(32 + 2*dp) * 8];
        #pragma unroll
        for (int k = 0; k < 8; k++) {
            float4 w = r0[k];
            acc[2*k+0] = f2fma(f0, pkp(w.x, w.y), acc[2*k+0]);
            acc[2*k+1] = f2fma(f0, pkp(w.z, w.w), acc[2*k+1]);
        }
        const float4* r1 = &sW1[(32 + 2*dp+1) * 8];
        #pragma unroll
        for (int k = 0; k < 8; k++) {
            float4 w = r1[k];
            acc[2*k+0] = f2fma(f1, pkp(w.x, w.y), acc[2*k+0]);
            acc[2*k+1] = f2fma(f1, pkp(w.z, w.w), acc[2*k+1]);
        }
    }
    #pragma unroll
    for (int d = 0; d < 16; d++) {
        ULL fd = pk2(ft[d]);
        const float4* r = &sW1[(64 + d) * 8];
        #pragma unroll
        for (int k = 0; k < 8; k++) {
            float4 w = r[k];
            acc[2*k+0] = f2fma(fd, pkp(w.x, w.y), acc[2*k+0]);
            acc[2*k+1] = f2fma(fd, pkp(w.z, w.w), acc[2*k+1]);
        }
    }

    float hid[32];
    #pragma unroll
    for (int q = 0; q < 16; q++) {
        float2 p = up2(acc[q]);
        hid[2*q+0] = fmaxf(p.x, 0.f);
        hid[2*q+1] = fmaxf(p.y, 0.f);
    }

    ULL o[8];
    #pragma unroll
    for (int q = 0; q < 8; q++) o[q] = 0ull;
    #pragma unroll
    for (int j = 0; j < 32; j++) {
        ULL hj = pk2(hid[j]);
        #pragma unroll
        for (int k = 0; k < 4; k++) {
            float4 w = sW2[j*4 + k];
            o[2*k+0] = f2fma(hj, pkp(w.x, w.y), o[2*k+0]);
            o[2*k+1] = f2fma(hj, pkp(w.z, w.w), o[2*k+1]);
        }
    }

    float4* op = reinterpret_cast<float4*>(out + (size_t)idx * D_EMB);
    #pragma unroll
    for (int q = 0; q < 4; q++) op[q] = mk4(o[2*q], o[2*q+1]);
}

// ---------------------------------------------------------------------------
extern "C" void kernel_launch(void* const* d_in, const int* in_sizes, int n_in,
                              void* d_out, int out_size) {
    const float* h_from_x   = (const float*)d_in[0];
    const float* h_from_z   = (const float*)d_in[1];
    const float* h_to       = (const float*)d_in[2];
    const int*   syndrome_x = (const int*)d_in[3];
    const int*   syndrome_z = (const int*)d_in[4];
    const int*   from_ind_x = (const int*)d_in[5];
    const int*   to_ind_x   = (const int*)d_in[6];
    const int*   from_ind_z = (const int*)d_in[7];
    const int*   to_ind_z   = (const int*)d_in[8];
    const float* Wx1        = (const float*)d_in[9];
    const float* Wx2        = (const float*)d_in[10];
    const float* Wz1        = (const float*)d_in[11];
    const float* Wz2        = (const float*)d_in[12];
    const float* We1        = (const float*)d_in[13];
    const float* We2        = (const float*)d_in[14];
    float* out = (float*)d_out;

    __half *hf_x, *hf_z, *s;
    float *M;
    int *cnt, *offs_x, *offs_z;
    unsigned *csr_x, *csr_z, *mask_x, *mask_z;
    cudaGetSymbolAddress((void**)&hf_x, g_hf_x);
    cudaGetSymbolAddress((void**)&hf_z, g_hf_z);
    cudaGetSymbolAddress((void**)&s,    g_s);
    cudaGetSymbolAddress((void**)&M,    g_M);
    cudaGetSymbolAddress((void**)&cnt,  g_cnt);
    cudaGetSymbolAddress((void**)&offs_x, g_offs_x);
    cudaGetSymbolAddress((void**)&offs_z, g_offs_z);
    cudaGetSymbolAddress((void**)&csr_x, g_csr_x);
    cudaGetSymbolAddress((void**)&csr_z, g_csr_z);
    cudaGetSymbolAddress((void**)&mask_x, g_mask_x);
    cudaGetSymbolAddress((void**)&mask_z, g_mask_z);

    int *deg_x = cnt, *deg_z = cnt + NUM_VN;
    int *cur_x = cnt + 2 * NUM_VN, *cur_z = cnt + 3 * NUM_VN;

    cudaMemsetAsync(cnt, 0, 4 * NUM_VN * sizeof(int), 0);

    // k1: histogram + masks
    prep_kernel<<<(NUM_E + 255) / 256, 256>>>(
        to_ind_x, to_ind_z, syndrome_x, syndrome_z,
        deg_x, deg_z, mask_x, mask_z);

    // k2: scan (blocks 0,1) + combined-matrix precompute (block 2)
    scan_kernel<<<3, 1024>>>(deg_x, deg_z, offs_x, offs_z, Wx2, Wz2, We1, M);

    // k3: fused CSR fill (y=2) + node partials (y=0,1)
    fill_np_kernel<<<dim3(12500, 3), 256>>>(
        from_ind_x, to_ind_x, from_ind_z, to_ind_z,
        offs_x, offs_z, mask_x, mask_z, cur_x, cur_z, csr_x, csr_z,
        h_from_x, h_from_z, Wx1, Wz1, hf_x, hf_z);

    // k4 (profiled slot): messages — half-batch warps, predicated uint2 gathers
    msg_kernel<<<dim3(12500, 2), 256>>>(
        h_to, hf_x, hf_z,
        offs_x, csr_x, offs_z, csr_z,
        Wx1, Wz1, s);

    // k5: vertex MLP with folded W2
    vn_kernel<<<(NUM_VN * B_SZ) / 256, 256>>>(s, h_to, M, We1, We2, out);
}

// round 13
// speedup vs baseline: 1.1458x; 1.1294x over previous
#include <cuda_runtime.h>
#include <cuda_fp16.h>

#define B_SZ   16
#define NUM_CN 25000
#define NUM_VN 50000
#define NUM_E  200000
#define D_EMB  16
#define D_HID  32
#define D_MSG  16

typedef unsigned long long ULL;

// ---- scratch (device globals) ----
__device__ __half g_hf_x[(size_t)NUM_CN * B_SZ * D_HID];   // [CN][B][32] fp16
__device__ __half g_hf_z[(size_t)NUM_CN * B_SZ * D_HID];
__device__ __half g_s[(size_t)2 * B_SZ * NUM_VN * D_HID];  // [pol][b][VN][32] fp16
__device__ float  g_M[2 * 32 * 32];                        // Mx | Mz combined mats
__device__ int      g_cnt[4 * NUM_VN];                     // deg_x|deg_z|cur_x|cur_z
__device__ int      g_offs_x[NUM_VN + 1], g_offs_z[NUM_VN + 1];
__device__ unsigned g_csr_x[NUM_E],   g_csr_z[NUM_E];      // f | (mask<<16)
__device__ unsigned g_mask_x[NUM_CN], g_mask_z[NUM_CN];

// ---------------------------------------------------------------------------
// f32x2 packed helpers
__device__ __forceinline__ ULL pk2(float x) {
    ULL d; asm("mov.b64 %0, {%1, %1};" : "=l"(d) : "f"(x)); return d;
}
__device__ __forceinline__ ULL pkp(float x, float y) {
    ULL d; asm("mov.b64 %0, {%1, %2};" : "=l"(d) : "f"(x), "f"(y)); return d;
}
__device__ __forceinline__ float2 up2(ULL a) {
    float lo, hi; asm("mov.b64 {%0, %1}, %2;" : "=f"(lo), "=f"(hi) : "l"(a));
    return make_float2(lo, hi);
}
__device__ __forceinline__ ULL f2fma(ULL a, ULL b, ULL c) {
    ULL d; asm("fma.rn.f32x2 %0, %1, %2, %3;" : "=l"(d) : "l"(a), "l"(b), "l"(c));
    return d;
}
__device__ __forceinline__ float4 mk4(ULL a, ULL b) {
    float2 p = up2(a), q = up2(b);
    return make_float4(p.x, p.y, q.x, q.y);
}

// ---------------------------------------------------------------------------
// kernel 1: fused prep (y=2: histogram + masks) + node partials (y=0,1)
__global__ void __launch_bounds__(256) prep_np_kernel(
    const int* __restrict__ to_x, const int* __restrict__ to_z,
    const int* __restrict__ syn_x, const int* __restrict__ syn_z,
    int* __restrict__ deg_x, int* __restrict__ deg_z,
    unsigned* __restrict__ mask_x, unsigned* __restrict__ mask_z,
    const float* __restrict__ hx, const float* __restrict__ hz,
    const float* __restrict__ Wx1, const float* __restrict__ Wz1,
    __half* __restrict__ ox, __half* __restrict__ oz)
{
    if (blockIdx.y == 2) {
        int i = blockIdx.x * 256 + threadIdx.x;
        if (i < NUM_E) {
            atomicAdd(&deg_x[__ldg(to_x + i)], 1);
            atomicAdd(&deg_z[__ldg(to_z + i)], 1);
        }
        if (i < NUM_CN) {
            unsigned mx = 0, mz = 0;
            #pragma unroll
            for (int b = 0; b < B_SZ; b++) {
                mx |= (unsigned)(__ldg(syn_x + (size_t)b * NUM_CN + i) & 1) << b;
                mz |= (unsigned)(__ldg(syn_z + (size_t)b * NUM_CN + i) & 1) << b;
            }
            mask_x[i] = mx;
            mask_z[i] = mz;
        }
        return;
    }

    const float* h  = blockIdx.y == 0 ? hx  : hz;
    const float* W1 = blockIdx.y == 0 ? Wx1 : Wz1;
    __half*      o  = blockIdx.y == 0 ? ox  : oz;

    __shared__ float4 sW1[128];   // W1 rows 0..15 (16x32)
    int t = threadIdx.x;
    if (t < 128) sW1[t] = reinterpret_cast<const float4*>(W1)[t];
    __syncthreads();

    int wid = t >> 5;
    int unit = blockIdx.x * 8 + wid;          // n*4 + bgroup, < 100000
    if (unit >= NUM_CN * 4) return;
    int n = unit >> 2;
    int b = ((unit & 3) << 2) | ((t >> 3) & 3);
    int chunk = t & 7;

    const float4* ph = reinterpret_cast<const float4*>(h + ((size_t)b * NUM_CN + n) * D_EMB);
    float4 h0 = ph[0], h1 = ph[1], h2 = ph[2], h3 = ph[3];
    float hr[16] = {h0.x,h0.y,h0.z,h0.w, h1.x,h1.y,h1.z,h1.w,
                    h2.x,h2.y,h2.z,h2.w, h3.x,h3.y,h3.z,h3.w};

    ULL a0 = 0ull, a1 = 0ull;
    #pragma unroll
    for (int d = 0; d < 16; d++) {
        float4 w = sW1[d*8 + chunk];
        ULL hd = pk2(hr[d]);
        a0 = f2fma(hd, pkp(w.x, w.y), a0);
        a1 = f2fma(hd, pkp(w.z, w.w), a1);
    }

    __half2 lo = __float22half2_rn(up2(a0));
    __half2 hi = __float22half2_rn(up2(a1));
    uint2 st;
    st.x = *reinterpret_cast<unsigned*>(&lo);
    st.y = *reinterpret_cast<unsigned*>(&hi);
    reinterpret_cast<uint2*>(o)[((size_t)n * B_SZ + b) * 8 + chunk] = st;
}

// ---------------------------------------------------------------------------
// kernel 2: exclusive scan (blocks 0,1) + combined-matrix precompute (block 2)
__global__ void __launch_bounds__(1024) scan_kernel(
    const int* __restrict__ deg_x, const int* __restrict__ deg_z,
    int* __restrict__ offs_x, int* __restrict__ offs_z,
    const float* __restrict__ Wx2, const float* __restrict__ Wz2,
    const float* __restrict__ We1, float* __restrict__ M)
{
    if (blockIdx.x == 2) {
        int t = threadIdx.x;
        #pragma unroll
        for (int r = 0; r < 2; r++) {
            int el = r * 1024 + t;            // 0..2047
            int pol = el >> 10;
            int i = (el >> 5) & 31;
            int j = el & 31;
            const float* W2 = pol ? Wz2 : Wx2;
            const float* E1 = We1 + pol * 16 * 32;
            float sum = 0.f;
            #pragma unroll
            for (int k = 0; k < 16; k++)
                sum += W2[i * 16 + k] * E1[k * 32 + j];
            M[el] = sum;
        }
        return;
    }

    const int* deg  = blockIdx.x == 0 ? deg_x  : deg_z;
    int*       offs = blockIdx.x == 0 ? offs_x : offs_z;

    __shared__ int wt[32];
    __shared__ int sbase;
    int t = threadIdx.x;
    int lane = t & 31, w = t >> 5;
    if (t == 0) sbase = 0;
    __syncthreads();

    for (int c = 0; c < NUM_VN; c += 1024) {
        int gid = c + t;
        int x = (gid < NUM_VN) ? deg[gid] : 0;
        #pragma unroll
        for (int o = 1; o < 32; o <<= 1) {
            int y = __shfl_up_sync(0xffffffffu, x, o);
            if (lane >= o) x += y;
        }
        if (lane == 31) wt[w] = x;
        __syncthreads();
        if (w == 0) {
            int y = wt[lane];
            #pragma unroll
            for (int o = 1; o < 32; o <<= 1) {
                int z = __shfl_up_sync(0xffffffffu, y, o);
                if (lane >= o) y += z;
            }
            wt[lane] = y;
        }
        __syncthreads();
        int incl = x + (w > 0 ? wt[w - 1] : 0) + sbase;
        if (gid < NUM_VN) offs[gid + 1] = incl;
        __syncthreads();
        if (t == 1023) sbase = incl;
        __syncthreads();
    }
    if (t == 0) offs[0] = 0;
}

// ---------------------------------------------------------------------------
// kernel 3: CSR fill
__global__ void __launch_bounds__(256) fill_kernel(
    const int* __restrict__ from_x, const int* __restrict__ to_x,
    const int* __restrict__ from_z, const int* __restrict__ to_z,
    const int* __restrict__ offs_x, const int* __restrict__ offs_z,
    const unsigned* __restrict__ mask_x, const unsigned* __restrict__ mask_z,
    int* __restrict__ cur_x, int* __restrict__ cur_z,
    unsigned* __restrict__ csr_x, unsigned* __restrict__ csr_z)
{
    int e = blockIdx.x * 256 + threadIdx.x;
    if (e >= NUM_E) return;
    {
        int v = __ldg(to_x + e);
        int f = __ldg(from_x + e);
        int p = atomicAdd(&cur_x[v], 1);
        csr_x[__ldg(offs_x + v) + p] = (unsigned)f | (__ldg(mask_x + f) << 16);
    }
    {
        int v = __ldg(to_z + e);
        int f = __ldg(from_z + e);
        int p = atomicAdd(&cur_z[v], 1);
        csr_z[__ldg(offs_z + v) + p] = (unsigned)f | (__ldg(mask_z + f) << 16);
    }
}

// ---------------------------------------------------------------------------
// kernel 4 (PROFILED SLOT): msg kernel — R10 structure (champion).
// warp = one v; lane = b_hi*8 + chunk; lane covers b = {0,1,2,3}*4 + b_hi.
// Per edge: ONE uniform csr load, ONE 32-bit base IMAD, FOUR independent
// predicated gathers (one per b-group). hp hoisted for all 4 b.
__global__ void __launch_bounds__(256) msg_kernel(
    const float* __restrict__ h_to,
    const __half* __restrict__ hfx, const __half* __restrict__ hfz,
    const int* __restrict__ offs_x, const unsigned* __restrict__ csr_x,
    const int* __restrict__ offs_z, const unsigned* __restrict__ csr_z,
    const float* __restrict__ Wx1, const float* __restrict__ Wz1,
    __half* __restrict__ s_out)
{
    int pol = blockIdx.y;
    const uint2*    hf2  = reinterpret_cast<const uint2*>(pol ? hfz : hfx);
    const int*      offs = pol ? offs_z : offs_x;
    const unsigned* csr  = pol ? csr_z  : csr_x;

    __shared__ float4 sW1[128];   // W1 rows 16..31 (16x32)
    {
        const float4* w1 = reinterpret_cast<const float4*>((pol ? Wz1 : Wx1) + 16 * 32);
        int t = threadIdx.x;
        if (t < 128) sW1[t] = w1[t];
    }
    __syncthreads();

    int t = threadIdx.x;
    int wid = t >> 5;
    int lane = t & 31;
    int v = blockIdx.x * 8 + wid;             // grid.x=6250 -> v in [0,50000)
    int b_hi = (lane >> 3) & 3;
    int chunk = lane & 7;

    // hoist hp for all 4 b-groups
    float2 hpa[4], hpb[4];
    #pragma unroll
    for (int bg = 0; bg < 4; bg++) {
        int b = bg * 4 + b_hi;
        const float4* ph = reinterpret_cast<const float4*>(
            h_to + ((size_t)b * NUM_VN + v) * D_EMB);
        float4 h0 = ph[0], h1 = ph[1], h2 = ph[2], h3 = ph[3];
        float hr[16] = {h0.x,h0.y,h0.z,h0.w, h1.x,h1.y,h1.z,h1.w,
                        h2.x,h2.y,h2.z,h2.w, h3.x,h3.y,h3.z,h3.w};
        ULL a0 = 0ull, a1 = 0ull;
        #pragma unroll
        for (int d = 0; d < 16; d++) {
            float4 w = sW1[d*8 + chunk];
            ULL hd = pk2(hr[d]);
            a0 = f2fma(hd, pkp(w.x, w.y), a0);
            a1 = f2fma(hd, pkp(w.z, w.w), a1);
        }
        hpa[bg] = up2(a0);
        hpb[bg] = up2(a1);
    }

    float s0[4] = {0,0,0,0}, s1[4] = {0,0,0,0};
    float s2[4] = {0,0,0,0}, s3[4] = {0,0,0,0};

    int beg = __ldg(offs + v), end = __ldg(offs + v + 1);
    unsigned shift0 = 16 + b_hi;
    unsigned lane_off = (unsigned)(b_hi * 8 + chunk);   // uint2 offset for bg=0

    for (int e = beg; e < end; e += 2) {
        unsigned pka = __ldg(csr + e);
        unsigned pkb = (e + 1 < end) ? __ldg(csr + e + 1) : 0u;

        unsigned basea = (pka & 0xFFFFu) * 128u + lane_off;
        unsigned baseb = (pkb & 0xFFFFu) * 128u + lane_off;

        uint2 va[4], vb[4];
        bool ga[4], gb[4];
        #pragma unroll
        for (int bg = 0; bg < 4; bg++) {
            ga[bg] = (pka >> (shift0 + bg * 4)) & 1u;
            gb[bg] = (pkb >> (shift0 + bg * 4)) & 1u;
            if (ga[bg]) va[bg] = __ldg(hf2 + basea + bg * 32u);
            if (gb[bg]) vb[bg] = __ldg(hf2 + baseb + bg * 32u);
        }
        #pragma unroll
        for (int bg = 0; bg < 4; bg++) {
            if (ga[bg]) {
                float2 lo = __half22float2(*reinterpret_cast<__half2*>(&va[bg].x));
                float2 hi = __half22float2(*reinterpret_cast<__half2*>(&va[bg].y));
                s0[bg] += fmaxf(lo.x + hpa[bg].x, 0.f);
                s1[bg] += fmaxf(lo.y + hpa[bg].y, 0.f);
                s2[bg] += fmaxf(hi.x + hpb[bg].x, 0.f);
                s3[bg] += fmaxf(hi.y + hpb[bg].y, 0.f);
            }
            if (gb[bg]) {
                float2 lo = __half22float2(*reinterpret_cast<__half2*>(&vb[bg].x));
                float2 hi = __half22float2(*reinterpret_cast<__half2*>(&vb[bg].y));
                s0[bg] += fmaxf(lo.x + hpa[bg].x, 0.f);
                s1[bg] += fmaxf(lo.y + hpa[bg].y, 0.f);
                s2[bg] += fmaxf(hi.x + hpb[bg].x, 0.f);
                s3[bg] += fmaxf(hi.y + hpb[bg].y, 0.f);
            }
        }
    }

    #pragma unroll
    for (int bg = 0; bg < 4; bg++) {
        int b = bg * 4 + b_hi;
        __half2 lo = __float22half2_rn(make_float2(s0[bg], s1[bg]));
        __half2 hi = __float22half2_rn(make_float2(s2[bg], s3[bg]));
        uint2 st;
        st.x = *reinterpret_cast<unsigned*>(&lo);
        st.y = *reinterpret_cast<unsigned*>(&hi);
        reinterpret_cast<uint2*>(s_out)[
            (((size_t)pol * B_SZ + b) * NUM_VN + v) * 8 + chunk] = st;
    }
}

// ---------------------------------------------------------------------------
// kernel 5: vn kernel — TWO rows per thread sharing weight LDS.
// out = relu(sx@Mx + sz@Mz + h_to@We1[32:48]) @ We2
__global__ void __launch_bounds__(160) vn_kernel(
    const __half* __restrict__ s, const float* __restrict__ h_to,
    const float* __restrict__ M, const float* __restrict__ We1,
    const float* __restrict__ We2, float* __restrict__ out)
{
    __shared__ float4 sW1[640];   // 80 rows x 32 cols: Mx(32) | Mz(32) | We1[32:48](16)
    __shared__ float4 sW2[128];   // We2 32x16
    int t = threadIdx.x;
    for (int i = t; i < 512; i += 160) sW1[i] = reinterpret_cast<const float4*>(M)[i];
    for (int i = t; i < 128; i += 160) {
        sW1[512 + i] = reinterpret_cast<const float4*>(We1 + 32 * 32)[i];
        sW2[i] = reinterpret_cast<const float4*>(We2)[i];
    }
    __syncthreads();

    int rA = blockIdx.x * 320 + t;        // rows: 2500 blocks * 320 = 800000
    int rB = rA + 160;
    const size_t BVN = (size_t)B_SZ * NUM_VN;

    ULL accA[16], accB[16];
    #pragma unroll
    for (int q = 0; q < 16; q++) { accA[q] = 0ull; accB[q] = 0ull; }

    // ---- sx (weight rows 0..31) and sz (rows 32..63), streamed ----
    #pragma unroll
    for (int pol = 0; pol < 2; pol++) {
        const uint4* pA = reinterpret_cast<const uint4*>(s) + ((size_t)pol * BVN + rA) * 4;
        const uint4* pB = reinterpret_cast<const uint4*>(s) + ((size_t)pol * BVN + rB) * 4;
        #pragma unroll
        for (int q = 0; q < 4; q++) {
            uint4 a = pA[q], b = pB[q];
            unsigned wa[4] = {a.x, a.y, a.z, a.w};
            unsigned wb[4] = {b.x, b.y, b.z, b.w};
            #pragma unroll
            for (int k = 0; k < 4; k++) {
                float2 fa = __half22float2(*reinterpret_cast<__half2*>(&wa[k]));
                float2 fb = __half22float2(*reinterpret_cast<__half2*>(&wb[k]));
                int d0 = pol * 32 + q * 8 + 2 * k;
                const float4* r0 = &sW1[d0 * 8];
                ULL fA0 = pk2(fa.x), fB0 = pk2(fb.x);
                #pragma unroll
                for (int kk = 0; kk < 8; kk++) {
                    float4 w = r0[kk];
                    ULL w01 = pkp(w.x, w.y), w23 = pkp(w.z, w.w);
                    accA[2*kk+0] = f2fma(fA0, w01, accA[2*kk+0]);
                    accA[2*kk+1] = f2fma(fA0, w23, accA[2*kk+1]);
                    accB[2*kk+0] = f2fma(fB0, w01, accB[2*kk+0]);
                    accB[2*kk+1] = f2fma(fB0, w23, accB[2*kk+1]);
                }
                const float4* r1 = &sW1[(d0 + 1) * 8];
                ULL fA1 = pk2(fa.y), fB1 = pk2(fb.y);
                #pragma unroll
                for (int kk = 0; kk < 8; kk++) {
                    float4 w = r1[kk];
                    ULL w01 = pkp(w.x, w.y), w23 = pkp(w.z, w.w);
                    accA[2*kk+0] = f2fma(fA1, w01, accA[2*kk+0]);
                    accA[2*kk+1] = f2fma(fA1, w23, accA[2*kk+1]);
                    accB[2*kk+0] = f2fma(fB1, w01, accB[2*kk+0]);
                    accB[2*kk+1] = f2fma(fB1, w23, accB[2*kk+1]);
                }
            }
        }
    }

    // ---- h_to (weight rows 64..79), streamed ----
    {
        const float4* phA = reinterpret_cast<const float4*>(h_to + (size_t)rA * D_EMB);
        const float4* phB = reinterpret_cast<const float4*>(h_to + (size_t)rB * D_EMB);
        #pragma unroll
        for (int q = 0; q < 4; q++) {
            float4 a = phA[q], b = phB[q];
            float fa[4] = {a.x, a.y, a.z, a.w};
            float fb[4] = {b.x, b.y, b.z, b.w};
            #pragma unroll
            for (int k = 0; k < 4; k++) {
                int d = 64 + q * 4 + k;
                const float4* r = &sW1[d * 8];
                ULL fA = pk2(fa[k]), fB = pk2(fb[k]);
                #pragma unroll
                for (int kk = 0; kk < 8; kk++) {
                    float4 w = r[kk];
                    ULL w01 = pkp(w.x, w.y), w23 = pkp(w.z, w.w);
                    accA[2*kk+0] = f2fma(fA, w01, accA[2*kk+0]);
                    accA[2*kk+1] = f2fma(fA, w23, accA[2*kk+1]);
                    accB[2*kk+0] = f2fma(fB, w01, accB[2*kk+0]);
                    accB[2*kk+1] = f2fma(fB, w23, accB[2*kk+1]);
                }
            }
        }
    }

    // relu
    float hidA[32], hidB[32];
    #pragma unroll
    for (int q = 0; q < 16; q++) {
        float2 pa = up2(accA[q]), pb = up2(accB[q]);
        hidA[2*q+0] = fmaxf(pa.x, 0.f);  hidA[2*q+1] = fmaxf(pa.y, 0.f);
        hidB[2*q+0] = fmaxf(pb.x, 0.f);  hidB[2*q+1] = fmaxf(pb.y, 0.f);
    }

    // GEMM2, shared weight LDS
    ULL oA[8], oB[8];
    #pragma unroll
    for (int q = 0; q < 8; q++) { oA[q] = 0ull; oB[q] = 0ull; }
    #pragma unroll
    for (int j = 0; j < 32; j++) {
        ULL hA = pk2(hidA[j]), hB = pk2(hidB[j]);
        #pragma unroll
        for (int k = 0; k < 4; k++) {
            float4 w = sW2[j*4 + k];
            ULL w01 = pkp(w.x, w.y), w23 = pkp(w.z, w.w);
            oA[2*k+0] = f2fma(hA, w01, oA[2*k+0]);
            oA[2*k+1] = f2fma(hA, w23, oA[2*k+1]);
            oB[2*k+0] = f2fma(hB, w01, oB[2*k+0]);
            oB[2*k+1] = f2fma(hB, w23, oB[2*k+1]);
        }
    }

    float4* opA = reinterpret_cast<float4*>(out + (size_t)rA * D_EMB);
    float4* opB = reinterpret_cast<float4*>(out + (size_t)rB * D_EMB);
    #pragma unroll
    for (int q = 0; q < 4; q++) {
        opA[q] = mk4(oA[2*q], oA[2*q+1]);
        opB[q] = mk4(oB[2*q], oB[2*q+1]);
    }
}

// ---------------------------------------------------------------------------
extern "C" void kernel_launch(void* const* d_in, const int* in_sizes, int n_in,
                              void* d_out, int out_size) {
    const float* h_from_x   = (const float*)d_in[0];
    const float* h_from_z   = (const float*)d_in[1];
    const float* h_to       = (const float*)d_in[2];
    const int*   syndrome_x = (const int*)d_in[3];
    const int*   syndrome_z = (const int*)d_in[4];
    const int*   from_ind_x = (const int*)d_in[5];
    const int*   to_ind_x   = (const int*)d_in[6];
    const int*   from_ind_z = (const int*)d_in[7];
    const int*   to_ind_z   = (const int*)d_in[8];
    const float* Wx1        = (const float*)d_in[9];
    const float* Wx2        = (const float*)d_in[10];
    const float* Wz1        = (const float*)d_in[11];
    const float* Wz2        = (const float*)d_in[12];
    const float* We1        = (const float*)d_in[13];
    const float* We2        = (const float*)d_in[14];
    float* out = (float*)d_out;

    __half *hf_x, *hf_z, *s;
    float *M;
    int *cnt, *offs_x, *offs_z;
    unsigned *csr_x, *csr_z, *mask_x, *mask_z;
    cudaGetSymbolAddress((void**)&hf_x, g_hf_x);
    cudaGetSymbolAddress((void**)&hf_z, g_hf_z);
    cudaGetSymbolAddress((void**)&s,    g_s);
    cudaGetSymbolAddress((void**)&M,    g_M);
    cudaGetSymbolAddress((void**)&cnt,  g_cnt);
    cudaGetSymbolAddress((void**)&offs_x, g_offs_x);
    cudaGetSymbolAddress((void**)&offs_z, g_offs_z);
    cudaGetSymbolAddress((void**)&csr_x, g_csr_x);
    cudaGetSymbolAddress((void**)&csr_z, g_csr_z);
    cudaGetSymbolAddress((void**)&mask_x, g_mask_x);
    cudaGetSymbolAddress((void**)&mask_z, g_mask_z);

    int *deg_x = cnt, *deg_z = cnt + NUM_VN;
    int *cur_x = cnt + 2 * NUM_VN, *cur_z = cnt + 3 * NUM_VN;

    cudaMemsetAsync(cnt, 0, 4 * NUM_VN * sizeof(int), 0);

    // k1: fused prep (y=2) + node partials (y=0,1) — np overlaps the prep chain
    prep_np_kernel<<<dim3(12500, 3), 256>>>(
        to_ind_x, to_ind_z, syndrome_x, syndrome_z,
        deg_x, deg_z, mask_x, mask_z,
        h_from_x, h_from_z, Wx1, Wz1, hf_x, hf_z);

    // k2: scan (blocks 0,1) + combined-matrix precompute (block 2)
    scan_kernel<<<3, 1024>>>(deg_x, deg_z, offs_x, offs_z, Wx2, Wz2, We1, M);

    // k3: CSR fill
    fill_kernel<<<(NUM_E + 255) / 256, 256>>>(
        from_ind_x, to_ind_x, from_ind_z, to_ind_z,
        offs_x, offs_z, mask_x, mask_z, cur_x, cur_z, csr_x, csr_z);

    // k4 (profiled slot): messages — R10 champion structure
    msg_kernel<<<dim3(6250, 2), 256>>>(
        h_to, hf_x, hf_z,
        offs_x, csr_x, offs_z, csr_z,
        Wx1, Wz1, s);

    // k5: vertex MLP — 2 rows/thread, shared weight LDS
    vn_kernel<<<2500, 160>>>(s, h_to, M, We1, We2, out);
}

// round 16
// speedup vs baseline: 1.4268x; 1.2453x over previous
#include <cuda_runtime.h>
#include <cuda_fp16.h>

#define B_SZ   16
#define NUM_CN 25000
#define NUM_VN 50000
#define NUM_E  200000
#define D_EMB  16
#define D_HID  32
#define D_MSG  16

typedef unsigned long long ULL;

// ---- scratch (device globals) ----
__device__ __half g_hf_x[(size_t)NUM_CN * B_SZ * D_HID];   // [CN][B][32] fp16
__device__ __half g_hf_z[(size_t)NUM_CN * B_SZ * D_HID];
__device__ __half g_s[(size_t)2 * B_SZ * NUM_VN * D_HID];  // [pol][b][VN][32] fp16
__device__ __half g_W1t[32 * 80];                          // transposed: [n][k], k<80
__device__ __half g_W2t[16 * 32];                          // transposed: [n][k], k<32
__device__ int      g_cnt[4 * NUM_VN];                     // deg_x|deg_z|cur_x|cur_z
__device__ int      g_offs_x[NUM_VN + 1], g_offs_z[NUM_VN + 1];
__device__ unsigned g_csr_x[NUM_E],   g_csr_z[NUM_E];      // f | (mask<<16)
__device__ unsigned g_mask_x[NUM_CN], g_mask_z[NUM_CN];

// ---------------------------------------------------------------------------
// f32x2 packed helpers
__device__ __forceinline__ ULL pk2(float x) {
    ULL d; asm("mov.b64 %0, {%1, %1};" : "=l"(d) : "f"(x)); return d;
}
__device__ __forceinline__ ULL pkp(float x, float y) {
    ULL d; asm("mov.b64 %0, {%1, %2};" : "=l"(d) : "f"(x), "f"(y)); return d;
}
__device__ __forceinline__ float2 up2(ULL a) {
    float lo, hi; asm("mov.b64 {%0, %1}, %2;" : "=f"(lo), "=f"(hi) : "l"(a));
    return make_float2(lo, hi);
}
__device__ __forceinline__ ULL f2fma(ULL a, ULL b, ULL c) {
    ULL d; asm("fma.rn.f32x2 %0, %1, %2, %3;" : "=l"(d) : "l"(a), "l"(b), "l"(c));
    return d;
}

// mma helper (no ldmatrix anywhere)
__device__ __forceinline__ void mma16816(float* c, unsigned a0, unsigned a1,
                                         unsigned a2, unsigned a3,
                                         unsigned b0, unsigned b1) {
    asm volatile(
        "mma.sync.aligned.m16n8k16.row.col.f32.f16.f16.f32 "
        "{%0,%1,%2,%3}, {%4,%5,%6,%7}, {%8,%9}, {%0,%1,%2,%3};"
        : "+f"(c[0]), "+f"(c[1]), "+f"(c[2]), "+f"(c[3])
        : "r"(a0), "r"(a1), "r"(a2), "r"(a3), "r"(b0), "r"(b1));
}
__device__ __forceinline__ unsigned packh2(float x, float y) {
    __half2 h = __float22half2_rn(make_float2(x, y));
    return *reinterpret_cast<unsigned*>(&h);
}
__device__ __forceinline__ unsigned ldh2(const __half* p) {
    return *reinterpret_cast<const unsigned*>(p);
}

// ---------------------------------------------------------------------------
// kernel 1: fused prep (y=2: histogram + masks) + node partials (y=0,1)
__global__ void __launch_bounds__(256) prep_np_kernel(
    const int* __restrict__ to_x, const int* __restrict__ to_z,
    const int* __restrict__ syn_x, const int* __restrict__ syn_z,
    int* __restrict__ deg_x, int* __restrict__ deg_z,
    unsigned* __restrict__ mask_x, unsigned* __restrict__ mask_z,
    const float* __restrict__ hx, const float* __restrict__ hz,
    const float* __restrict__ Wx1, const float* __restrict__ Wz1,
    __half* __restrict__ ox, __half* __restrict__ oz)
{
    if (blockIdx.y == 2) {
        int i = blockIdx.x * 256 + threadIdx.x;
        if (i < NUM_E) {
            atomicAdd(&deg_x[__ldg(to_x + i)], 1);
            atomicAdd(&deg_z[__ldg(to_z + i)], 1);
        }
        if (i < NUM_CN) {
            unsigned mx = 0, mz = 0;
            #pragma unroll
            for (int b = 0; b < B_SZ; b++) {
                mx |= (unsigned)(__ldg(syn_x + (size_t)b * NUM_CN + i) & 1) << b;
                mz |= (unsigned)(__ldg(syn_z + (size_t)b * NUM_CN + i) & 1) << b;
            }
            mask_x[i] = mx;
            mask_z[i] = mz;
        }
        return;
    }

    const float* h  = blockIdx.y == 0 ? hx  : hz;
    const float* W1 = blockIdx.y == 0 ? Wx1 : Wz1;
    __half*      o  = blockIdx.y == 0 ? ox  : oz;

    __shared__ float4 sW1[128];   // W1 rows 0..15 (16x32)
    int t = threadIdx.x;
    if (t < 128) sW1[t] = reinterpret_cast<const float4*>(W1)[t];
    __syncthreads();

    int wid = t >> 5;
    int unit = blockIdx.x * 8 + wid;          // n*4 + bgroup, < 100000
    if (unit >= NUM_CN * 4) return;
    int n = unit >> 2;
    int b = ((unit & 3) << 2) | ((t >> 3) & 3);
    int chunk = t & 7;

    const float4* ph = reinterpret_cast<const float4*>(h + ((size_t)b * NUM_CN + n) * D_EMB);
    float4 h0 = ph[0], h1 = ph[1], h2 = ph[2], h3 = ph[3];
    float hr[16] = {h0.x,h0.y,h0.z,h0.w, h1.x,h1.y,h1.z,h1.w,
                    h2.x,h2.y,h2.z,h2.w, h3.x,h3.y,h3.z,h3.w};

    ULL a0 = 0ull, a1 = 0ull;
    #pragma unroll
    for (int d = 0; d < 16; d++) {
        float4 w = sW1[d*8 + chunk];
        ULL hd = pk2(hr[d]);
        a0 = f2fma(hd, pkp(w.x, w.y), a0);
        a1 = f2fma(hd, pkp(w.z, w.w), a1);
    }

    __half2 lo = __float22half2_rn(up2(a0));
    __half2 hi = __float22half2_rn(up2(a1));
    uint2 st;
    st.x = *reinterpret_cast<unsigned*>(&lo);
    st.y = *reinterpret_cast<unsigned*>(&hi);
    reinterpret_cast<uint2*>(o)[((size_t)n * B_SZ + b) * 8 + chunk] = st;
}

// ---------------------------------------------------------------------------
// kernel 2: exclusive scan (blocks 0,1) + TRANSPOSED fp16 weight precompute (block 2)
// W1t[n][k]: k 0..31 = Mx col n, k 32..63 = Mz, k 64..79 = We1[32:48]
__global__ void __launch_bounds__(1024) scan_kernel(
    const int* __restrict__ deg_x, const int* __restrict__ deg_z,
    int* __restrict__ offs_x, int* __restrict__ offs_z,
    const float* __restrict__ Wx2, const float* __restrict__ Wz2,
    const float* __restrict__ We1, const float* __restrict__ We2,
    __half* __restrict__ W1t, __half* __restrict__ W2t)
{
    if (blockIdx.x == 2) {
        int t = threadIdx.x;
        #pragma unroll
        for (int r = 0; r < 2; r++) {
            int el = r * 1024 + t;            // 0..2047 : Mx | Mz
            int pol = el >> 10;
            int i = (el >> 5) & 31;           // k within pol block
            int j = el & 31;                  // n
            const float* W2 = pol ? Wz2 : Wx2;
            const float* E1 = We1 + pol * 16 * 32;
            float sum = 0.f;
            #pragma unroll
            for (int k = 0; k < 16; k++)
                sum += W2[i * 16 + k] * E1[k * 32 + j];
            W1t[j * 80 + pol * 32 + i] = __float2half(sum);
        }
        if (t < 512) {
            int d = t >> 5, j = t & 31;       // We1 tail rows 32..47
            W1t[j * 80 + 64 + d] = __float2half(We1[(32 + d) * 32 + j]);
        } else {
            int idx = t - 512;                // We2 transpose: [16][32]
            int k = idx >> 4, n = idx & 15;
            W2t[n * 32 + k] = __float2half(We2[k * 16 + n]);
        }
        return;
    }

    const int* deg  = blockIdx.x == 0 ? deg_x  : deg_z;
    int*       offs = blockIdx.x == 0 ? offs_x : offs_z;

    __shared__ int wt[32];
    __shared__ int sbase;
    int t = threadIdx.x;
    int lane = t & 31, w = t >> 5;
    if (t == 0) sbase = 0;
    __syncthreads();

    for (int c = 0; c < NUM_VN; c += 1024) {
        int gid = c + t;
        int x = (gid < NUM_VN) ? deg[gid] : 0;
        #pragma unroll
        for (int o = 1; o < 32; o <<= 1) {
            int y = __shfl_up_sync(0xffffffffu, x, o);
            if (lane >= o) x += y;
        }
        if (lane == 31) wt[w] = x;
        __syncthreads();
        if (w == 0) {
            int y = wt[lane];
            #pragma unroll
            for (int o = 1; o < 32; o <<= 1) {
                int z = __shfl_up_sync(0xffffffffu, y, o);
                if (lane >= o) y += z;
            }
            wt[lane] = y;
        }
        __syncthreads();
        int incl = x + (w > 0 ? wt[w - 1] : 0) + sbase;
        if (gid < NUM_VN) offs[gid + 1] = incl;
        __syncthreads();
        if (t == 1023) sbase = incl;
        __syncthreads();
    }
    if (t == 0) offs[0] = 0;
}

// ---------------------------------------------------------------------------
// kernel 3: CSR fill
__global__ void __launch_bounds__(256) fill_kernel(
    const int* __restrict__ from_x, const int* __restrict__ to_x,
    const int* __restrict__ from_z, const int* __restrict__ to_z,
    const int* __restrict__ offs_x, const int* __restrict__ offs_z,
    const unsigned* __restrict__ mask_x, const unsigned* __restrict__ mask_z,
    int* __restrict__ cur_x, int* __restrict__ cur_z,
    unsigned* __restrict__ csr_x, unsigned* __restrict__ csr_z)
{
    int e = blockIdx.x * 256 + threadIdx.x;
    if (e >= NUM_E) return;
    {
        int v = __ldg(to_x + e);
        int f = __ldg(from_x + e);
        int p = atomicAdd(&cur_x[v], 1);
        csr_x[__ldg(offs_x + v) + p] = (unsigned)f | (__ldg(mask_x + f) << 16);
    }
    {
        int v = __ldg(to_z + e);
        int f = __ldg(from_z + e);
        int p = atomicAdd(&cur_z[v], 1);
        csr_z[__ldg(offs_z + v) + p] = (unsigned)f | (__ldg(mask_z + f) << 16);
    }
}

// ---------------------------------------------------------------------------
// kernel 4 (PROFILED SLOT): msg kernel — R10 champion structure.
__global__ void __launch_bounds__(256) msg_kernel(
    const float* __restrict__ h_to,
    const __half* __restrict__ hfx, const __half* __restrict__ hfz,
    const int* __restrict__ offs_x, const unsigned* __restrict__ csr_x,
    const int* __restrict__ offs_z, const unsigned* __restrict__ csr_z,
    const float* __restrict__ Wx1, const float* __restrict__ Wz1,
    __half* __restrict__ s_out)
{
    int pol = blockIdx.y;
    const uint2*    hf2  = reinterpret_cast<const uint2*>(pol ? hfz : hfx);
    const int*      offs = pol ? offs_z : offs_x;
    const unsigned* csr  = pol ? csr_z  : csr_x;

    __shared__ float4 sW1[128];   // W1 rows 16..31 (16x32)
    {
        const float4* w1 = reinterpret_cast<const float4*>((pol ? Wz1 : Wx1) + 16 * 32);
        int t = threadIdx.x;
        if (t < 128) sW1[t] = w1[t];
    }
    __syncthreads();

    int t = threadIdx.x;
    int wid = t >> 5;
    int lane = t & 31;
    int v = blockIdx.x * 8 + wid;             // grid.x=6250 -> v in [0,50000)
    int b_hi = (lane >> 3) & 3;
    int chunk = lane & 7;

    float2 hpa[4], hpb[4];
    #pragma unroll
    for (int bg = 0; bg < 4; bg++) {
        int b = bg * 4 + b_hi;
        const float4* ph = reinterpret_cast<const float4*>(
            h_to + ((size_t)b * NUM_VN + v) * D_EMB);
        float4 h0 = ph[0], h1 = ph[1], h2 = ph[2], h3 = ph[3];
        float hr[16] = {h0.x,h0.y,h0.z,h0.w, h1.x,h1.y,h1.z,h1.w,
                        h2.x,h2.y,h2.z,h2.w, h3.x,h3.y,h3.z,h3.w};
        ULL a0 = 0ull, a1 = 0ull;
        #pragma unroll
        for (int d = 0; d < 16; d++) {
            float4 w = sW1[d*8 + chunk];
            ULL hd = pk2(hr[d]);
            a0 = f2fma(hd, pkp(w.x, w.y), a0);
            a1 = f2fma(hd, pkp(w.z, w.w), a1);
        }
        hpa[bg] = up2(a0);
        hpb[bg] = up2(a1);
    }

    float s0[4] = {0,0,0,0}, s1[4] = {0,0,0,0};
    float s2[4] = {0,0,0,0}, s3[4] = {0,0,0,0};

    int beg = __ldg(offs + v), end = __ldg(offs + v + 1);
    unsigned shift0 = 16 + b_hi;
    unsigned lane_off = (unsigned)(b_hi * 8 + chunk);

    for (int e = beg; e < end; e += 2) {
        unsigned pka = __ldg(csr + e);
        unsigned pkb = (e + 1 < end) ? __ldg(csr + e + 1) : 0u;

        unsigned basea = (pka & 0xFFFFu) * 128u + lane_off;
        unsigned baseb = (pkb & 0xFFFFu) * 128u + lane_off;

        uint2 va[4], vb[4];
        bool ga[4], gb[4];
        #pragma unroll
        for (int bg = 0; bg < 4; bg++) {
            ga[bg] = (pka >> (shift0 + bg * 4)) & 1u;
            gb[bg] = (pkb >> (shift0 + bg * 4)) & 1u;
            if (ga[bg]) va[bg] = __ldg(hf2 + basea + bg * 32u);
            if (gb[bg]) vb[bg] = __ldg(hf2 + baseb + bg * 32u);
        }
        #pragma unroll
        for (int bg = 0; bg < 4; bg++) {
            if (ga[bg]) {
                float2 lo = __half22float2(*reinterpret_cast<__half2*>(&va[bg].x));
                float2 hi = __half22float2(*reinterpret_cast<__half2*>(&va[bg].y));
                s0[bg] += fmaxf(lo.x + hpa[bg].x, 0.f);
                s1[bg] += fmaxf(lo.y + hpa[bg].y, 0.f);
                s2[bg] += fmaxf(hi.x + hpb[bg].x, 0.f);
                s3[bg] += fmaxf(hi.y + hpb[bg].y, 0.f);
            }
            if (gb[bg]) {
                float2 lo = __half22float2(*reinterpret_cast<__half2*>(&vb[bg].x));
                float2 hi = __half22float2(*reinterpret_cast<__half2*>(&vb[bg].y));
                s0[bg] += fmaxf(lo.x + hpa[bg].x, 0.f);
                s1[bg] += fmaxf(lo.y + hpa[bg].y, 0.f);
                s2[bg] += fmaxf(hi.x + hpb[bg].x, 0.f);
                s3[bg] += fmaxf(hi.y + hpb[bg].y, 0.f);
            }
        }
    }

    #pragma unroll
    for (int bg = 0; bg < 4; bg++) {
        int b = bg * 4 + b_hi;
        __half2 lo = __float22half2_rn(make_float2(s0[bg], s1[bg]));
        __half2 hi = __float22half2_rn(make_float2(s2[bg], s3[bg]));
        uint2 st;
        st.x = *reinterpret_cast<unsigned*>(&lo);
        st.y = *reinterpret_cast<unsigned*>(&hi);
        reinterpret_cast<uint2*>(s_out)[
            (((size_t)pol * B_SZ + b) * NUM_VN + v) * 8 + chunk] = st;
    }
}

// ---------------------------------------------------------------------------
// kernel 5: vn kernel — HMMA with DIRECT fragment loads (no ldmatrix).
// Warp = one 16-row tile. A fragment coords (m16n8k16, row-major A):
//   r = lane>>2, c = (lane&3)*2
//   a0=A[r][c,c+1]  a1=A[r+8][c,c+1]  a2=A[r][c+8,c+9]  a3=A[r+8][c+8,c+9]
// B (col fragment) from transposed weights Wt[n][k]:
//   b0=Wt[n][c,c+1], b1=Wt[n][c+8,c+9], with n = nn*8 + (lane>>2)
#define A_STRIDE 88
#define W_STRIDE 88

__global__ void __launch_bounds__(256) vn_kernel(
    const __half* __restrict__ s, const float* __restrict__ h_to,
    const __half* __restrict__ W1t, const __half* __restrict__ W2t,
    float* __restrict__ out)
{
    __shared__ __align__(16) __half W1s[32 * W_STRIDE];
    __shared__ __align__(16) __half W2s[16 * W_STRIDE];
    __shared__ __align__(16) __half As[8][16 * A_STRIDE];

    int t = threadIdx.x;
    // stage transposed weights: W1t 32 rows x 10 uint4; W2t 16 rows x 4 uint4
    for (int i = t; i < 320; i += 256) {
        int r = i / 10, q = i - r * 10;
        *reinterpret_cast<uint4*>(&W1s[r * W_STRIDE + q * 8]) =
            reinterpret_cast<const uint4*>(W1t)[i];
    }
    for (int i = t; i < 64; i += 256) {
        int r = i >> 2, q = i & 3;
        *reinterpret_cast<uint4*>(&W2s[r * W_STRIDE + q * 8]) =
            reinterpret_cast<const uint4*>(W2t)[i];
    }
    __syncthreads();

    int wid = t >> 5;
    int lane = t & 31;
    int tile = blockIdx.x * 8 + wid;            // 50000 tiles total
    int rbase = tile * 16;
    __half* A = &As[wid][0];
    const size_t BVN = (size_t)B_SZ * NUM_VN;

    // ---- stage feat tile: cols 0-31 sx, 32-63 sz, 64-79 h_to(fp16) ----
    {
        const uint4* px = reinterpret_cast<const uint4*>(s) + (size_t)rbase * 4;
        const uint4* pz = reinterpret_cast<const uint4*>(s) + (BVN + rbase) * 4;
        #pragma unroll
        for (int i = lane; i < 64; i += 32) {
            int r = i >> 2, q = i & 3;
            *reinterpret_cast<uint4*>(&A[r * A_STRIDE + q * 8])      = __ldg(px + i);
            *reinterpret_cast<uint4*>(&A[r * A_STRIDE + 32 + q * 8]) = __ldg(pz + i);
        }
        const float4* ph = reinterpret_cast<const float4*>(h_to + (size_t)rbase * D_EMB);
        #pragma unroll
        for (int i = lane; i < 64; i += 32) {
            int r = i >> 2, q = i & 3;
            float4 v = __ldg(ph + i);
            uint2 u;
            u.x = packh2(v.x, v.y);
            u.y = packh2(v.z, v.w);
            *reinterpret_cast<uint2*>(&A[r * A_STRIDE + 64 + q * 4]) = u;
        }
    }
    __syncwarp();

    int r = lane >> 2;
    int c = (lane & 3) * 2;

    // ---- GEMM1: C[16x32] = feat[16x80] @ W1[80x32] (5 k-steps x 4 n-tiles) ----
    float cf[4][4];
    #pragma unroll
    for (int nn = 0; nn < 4; nn++)
        #pragma unroll
        for (int k = 0; k < 4; k++) cf[nn][k] = 0.f;

    #pragma unroll
    for (int kk = 0; kk < 5; kk++) {
        int ka = kk * 16 + c;
        unsigned a0 = ldh2(&A[r * A_STRIDE + ka]);
        unsigned a1 = ldh2(&A[(r + 8) * A_STRIDE + ka]);
        unsigned a2 = ldh2(&A[r * A_STRIDE + ka + 8]);
        unsigned a3 = ldh2(&A[(r + 8) * A_STRIDE + ka + 8]);
        #pragma unroll
        for (int nn = 0; nn < 4; nn++) {
            const __half* wrow = &W1s[(nn * 8 + r) * W_STRIDE + ka];
            unsigned b0 = ldh2(wrow);
            unsigned b1 = ldh2(wrow + 8);
            mma16816(cf[nn], a0, a1, a2, a3, b0, b1);
        }
    }

    // ---- relu + C->A repack, GEMM2: out[16x16] = hid[16x32] @ W2[32x16] ----
    float d[2][4];
    #pragma unroll
    for (int nn = 0; nn < 2; nn++)
        #pragma unroll
        for (int k = 0; k < 4; k++) d[nn][k] = 0.f;

    #pragma unroll
    for (int kk2 = 0; kk2 < 2; kk2++) {
        int lo = kk2 * 2, hi = kk2 * 2 + 1;
        unsigned a0 = packh2(fmaxf(cf[lo][0], 0.f), fmaxf(cf[lo][1], 0.f));
        unsigned a1 = packh2(fmaxf(cf[lo][2], 0.f), fmaxf(cf[lo][3], 0.f));
        unsigned a2 = packh2(fmaxf(cf[hi][0], 0.f), fmaxf(cf[hi][1], 0.f));
        unsigned a3 = packh2(fmaxf(cf[hi][2], 0.f), fmaxf(cf[hi][3], 0.f));
        int ka = kk2 * 16 + c;
        #pragma unroll
        for (int nn = 0; nn < 2; nn++) {
            const __half* wrow = &W2s[(nn * 8 + r) * W_STRIDE + ka];
            unsigned b0 = ldh2(wrow);
            unsigned b1 = ldh2(wrow + 8);
            mma16816(d[nn], a0, a1, a2, a3, b0, b1);
        }
    }

    // ---- store: out row-major [800k][16] fp32 ----
    int tt = lane & 3;
    #pragma unroll
    for (int nn = 0; nn < 2; nn++) {
        float2 lo = make_float2(d[nn][0], d[nn][1]);
        float2 hi = make_float2(d[nn][2], d[nn][3]);
        *reinterpret_cast<float2*>(out + ((size_t)rbase + r)     * 16 + nn * 8 + tt * 2) = lo;
        *reinterpret_cast<float2*>(out + ((size_t)rbase + r + 8) * 16 + nn * 8 + tt * 2) = hi;
    }
}

// ---------------------------------------------------------------------------
extern "C" void kernel_launch(void* const* d_in, const int* in_sizes, int n_in,
                              void* d_out, int out_size) {
    const float* h_from_x   = (const float*)d_in[0];
    const float* h_from_z   = (const float*)d_in[1];
    const float* h_to       = (const float*)d_in[2];
    const int*   syndrome_x = (const int*)d_in[3];
    const int*   syndrome_z = (const int*)d_in[4];
    const int*   from_ind_x = (const int*)d_in[5];
    const int*   to_ind_x   = (const int*)d_in[6];
    const int*   from_ind_z = (const int*)d_in[7];
    const int*   to_ind_z   = (const int*)d_in[8];
    const float* Wx1        = (const float*)d_in[9];
    const float* Wx2        = (const float*)d_in[10];
    const float* Wz1        = (const float*)d_in[11];
    const float* Wz2        = (const float*)d_in[12];
    const float* We1        = (const float*)d_in[13];
    const float* We2        = (const float*)d_in[14];
    float* out = (float*)d_out;

    __half *hf_x, *hf_z, *s, *W1t, *W2t;
    int *cnt, *offs_x, *offs_z;
    unsigned *csr_x, *csr_z, *mask_x, *mask_z;
    cudaGetSymbolAddress((void**)&hf_x, g_hf_x);
    cudaGetSymbolAddress((void**)&hf_z, g_hf_z);
    cudaGetSymbolAddress((void**)&s,    g_s);
    cudaGetSymbolAddress((void**)&W1t,  g_W1t);
    cudaGetSymbolAddress((void**)&W2t,  g_W2t);
    cudaGetSymbolAddress((void**)&cnt,  g_cnt);
    cudaGetSymbolAddress((void**)&offs_x, g_offs_x);
    cudaGetSymbolAddress((void**)&offs_z, g_offs_z);
    cudaGetSymbolAddress((void**)&csr_x, g_csr_x);
    cudaGetSymbolAddress((void**)&csr_z, g_csr_z);
    cudaGetSymbolAddress((void**)&mask_x, g_mask_x);
    cudaGetSymbolAddress((void**)&mask_z, g_mask_z);

    int *deg_x = cnt, *deg_z = cnt + NUM_VN;
    int *cur_x = cnt + 2 * NUM_VN, *cur_z = cnt + 3 * NUM_VN;

    cudaMemsetAsync(cnt, 0, 4 * NUM_VN * sizeof(int), 0);

    // k1: fused prep (y=2) + node partials (y=0,1)
    prep_np_kernel<<<dim3(12500, 3), 256>>>(
        to_ind_x, to_ind_z, syndrome_x, syndrome_z,
        deg_x, deg_z, mask_x, mask_z,
        h_from_x, h_from_z, Wx1, Wz1, hf_x, hf_z);

    // k2: scan (blocks 0,1) + transposed fp16 weight precompute (block 2)
    scan_kernel<<<3, 1024>>>(deg_x, deg_z, offs_x, offs_z,
                             Wx2, Wz2, We1, We2, W1t, W2t);

    // k3: CSR fill
    fill_kernel<<<(NUM_E + 255) / 256, 256>>>(
        from_ind_x, to_ind_x, from_ind_z, to_ind_z,
        offs_x, offs_z, mask_x, mask_z, cur_x, cur_z, csr_x, csr_z);

    // k4 (profiled slot): messages — R10 champion structure
    msg_kernel<<<dim3(6250, 2), 256>>>(
        h_to, hf_x, hf_z,
        offs_x, csr_x, offs_z, csr_z,
        Wx1, Wz1, s);

    // k5: vertex MLP — HMMA, direct fragment loads
    vn_kernel<<<6250, 256>>>(s, h_to, W1t, W2t, out);
}